// round 11
// baseline (speedup 1.0000x reference)
#include <cuda_runtime.h>
#include <cuda_fp16.h>

#define BPTS   16384
#define NE     8
#define CHUNKD 32
#define EPSF   2.220446049250313e-16f
#define WROWS  1728           // padded expert K rows: 96+4*256+256+96+256
#define GWROWS 576            // gate: 320 (gw1 padded) + 256 (gw2)
#define NT     256
#define MR     32             // rows per CTA tile
typedef unsigned int u32;
typedef unsigned short u16;

// ---------------- scratch (static device globals) ----------------------------
__device__ int   g_count[NE];
__device__ int   g_list[NE][BPTS];
__device__ float g_gv[BPTS];
// expert weights row-major [e][k][n(256)] fp16 hi / lo (rows permuted: see prep)
__device__ u16 g_wh[NE * WROWS * 256];
__device__ u16 g_wl[NE * WROWS * 256];
// gate weights [k(576)][n(256)] fp16 hi / lo (rows permuted)
__device__ u16 g_gh[GWROWS * 256];
__device__ u16 g_gl[GWROWS * 256];

// ---------------- tensor-core helpers ----------------------------------------
__device__ __forceinline__ void mma_f16(float d[4], u32 a0, u32 a1, u32 a2, u32 a3,
                                        u32 b0, u32 b1) {
    asm volatile(
        "mma.sync.aligned.m16n8k16.row.col.f32.f16.f16.f32 "
        "{%0,%1,%2,%3}, {%4,%5,%6,%7}, {%8,%9}, {%0,%1,%2,%3};"
        : "+f"(d[0]), "+f"(d[1]), "+f"(d[2]), "+f"(d[3])
        : "r"(a0), "r"(a1), "r"(a2), "r"(a3), "r"(b0), "r"(b1));
}
__device__ __forceinline__ void ldsm4(u32 r[4], u32 addr) {
    asm volatile("ldmatrix.sync.aligned.m8n8.x4.shared.b16 {%0,%1,%2,%3}, [%4];"
                 : "=r"(r[0]), "=r"(r[1]), "=r"(r[2]), "=r"(r[3]) : "r"(addr));
}
__device__ __forceinline__ void ldsm4t(u32 r[4], u32 addr) {
    asm volatile("ldmatrix.sync.aligned.m8n8.x4.trans.shared.b16 {%0,%1,%2,%3}, [%4];"
                 : "=r"(r[0]), "=r"(r[1]), "=r"(r[2]), "=r"(r[3]) : "r"(addr));
}
#define CP16(dst, src) \
    asm volatile("cp.async.cg.shared.global [%0], [%1], 16;" :: "r"(dst), "l"(src))
#define CPCOMMIT() asm volatile("cp.async.commit_group;")
#define CPWAIT0()  asm volatile("cp.async.wait_group 0;")

__device__ __forceinline__ void split2h(float v, u16& h, u16& l) {
    __half hh = __float2half_rn(v);
    __half ll = __float2half_rn(v - __half2float(hh));
    h = *(u16*)&hh;  l = *(u16*)&ll;
}
__device__ __forceinline__ void split4_store(float4 v, u16* dh, u16* dl) {
    __half2 h01 = __floats2half2_rn(v.x, v.y);
    __half2 h23 = __floats2half2_rn(v.z, v.w);
    float2 f01 = __half22float2(h01), f23 = __half22float2(h23);
    __half2 l01 = __floats2half2_rn(v.x - f01.x, v.y - f01.y);
    __half2 l23 = __floats2half2_rn(v.z - f23.x, v.w - f23.y);
    ((u32*)dh)[0] = *(u32*)&h01; ((u32*)dh)[1] = *(u32*)&h23;
    ((u32*)dl)[0] = *(u32*)&l01; ((u32*)dl)[1] = *(u32*)&l23;
}

// ---------------- weight chunk staging (16 k-rows, hi+lo) ---------------------
// smem plane rows stride 264 u16 (528 B); lo plane at +8448 B. Buffer 16896 B.
__device__ __forceinline__ void stage_chunk16(
    u32 dst_base, const u16* __restrict__ Wh, const u16* __restrict__ Wl,
    int c, int tid) {
#pragma unroll
    for (int p = 0; p < 4; p++) {
        int uu = tid + p * NT;          // 0..1023
        int isLo = uu >> 9;
        int v = uu & 511;
        int row = v >> 5, col = v & 31;
        const u16* src = (isLo ? Wl : Wh) + (size_t)(c * 16 + row) * 256 + col * 8;
        u32 dst = dst_base + isLo * 8448 + row * 528 + col * 16;
        CP16(dst, src);
    }
}

// GEMM: acc[32x256] += A[32xK] @ W[Kx256]; A pre-split fp16 hi/lo planes in
// smem (ldmatrix), W staged hi/lo via cp.async double-buffered 16-row chunks.
// 8 warps: warp grid 1(M=32) x 8(N=32); acc[2][4][4] per thread.
__device__ __forceinline__ void gemm_tc3(
    float (&acc)[2][4][4],
    u32 a_hi_b, u32 a_lo_b, int rowbytes,
    const u16* __restrict__ Wh, const u16* __restrict__ Wl,
    int nc, u32 wstu, u32 bboff, int tid)
{
    stage_chunk16(wstu, Wh, Wl, 0, tid);
    CPCOMMIT();
    u32 ah[2][4], al[2][4], bh[4], bl[4];
    for (int c = 0; c < nc; c++) {
        CPWAIT0();
        __syncthreads();
        if (c + 1 < nc) {
            stage_chunk16(wstu + ((c + 1) & 1) * 16896, Wh, Wl, c + 1, tid);
            CPCOMMIT();
        }
        const u32 cur = wstu + (c & 1) * 16896;
        const u32 aoff = (u32)(c * 32);
        ldsm4(ah[0], a_hi_b + aoff);
        ldsm4(ah[1], a_hi_b + 16 * rowbytes + aoff);
        ldsm4(al[0], a_lo_b + aoff);
        ldsm4(al[1], a_lo_b + 16 * rowbytes + aoff);
        const u32 bb = cur + bboff;
#pragma unroll
        for (int gg = 0; gg < 2; gg++) {
            ldsm4t(bh, bb + gg * 32);
            ldsm4t(bl, bb + 8448 + gg * 32);
#pragma unroll
            for (int nb = 0; nb < 2; nb++) {
                const int j = gg * 2 + nb;
                const u32 b0 = bh[2 * nb], b1 = bh[2 * nb + 1];
                const u32 c0 = bl[2 * nb], c1 = bl[2 * nb + 1];
#pragma unroll
                for (int im = 0; im < 2; im++) {
                    mma_f16(acc[im][j], ah[im][0], ah[im][1], ah[im][2], ah[im][3], b0, b1);
                    mma_f16(acc[im][j], al[im][0], al[im][1], al[im][2], al[im][3], b0, b1);
                    mma_f16(acc[im][j], ah[im][0], ah[im][1], ah[im][2], ah[im][3], c0, c1);
                }
            }
        }
    }
}

__device__ __forceinline__ void zero_acc_tc(float (&acc)[2][4][4]) {
#pragma unroll
    for (int im = 0; im < 2; im++)
#pragma unroll
        for (int j = 0; j < 4; j++)
#pragma unroll
            for (int q = 0; q < 4; q++) acc[im][j][q] = 0.f;
}

// epilogue: relu(acc+bias) -> split fp16 hi/lo planes (stride 264); M=32 rows
__device__ __forceinline__ void epi_relu(const float (&acc)[2][4][4],
                                         const float* __restrict__ bias,
                                         u16* a_hi, u16* a_lo, int tid) {
    const int lane = tid & 31, wid = tid >> 5;
    const int n_off = wid * 32;
    const int g = lane >> 2, tt = lane & 3;
#pragma unroll
    for (int im = 0; im < 2; im++)
#pragma unroll
        for (int j = 0; j < 4; j++) {
            const int c = n_off + j * 8 + 2 * tt;
            const float b0 = bias[c], b1 = bias[c + 1];
            const int rlo = im * 16 + g, rhi = rlo + 8;
            float v0 = fmaxf(acc[im][j][0] + b0, 0.f);
            float v1 = fmaxf(acc[im][j][1] + b1, 0.f);
            float v2 = fmaxf(acc[im][j][2] + b0, 0.f);
            float v3 = fmaxf(acc[im][j][3] + b1, 0.f);
            __half2 h01 = __floats2half2_rn(v0, v1);
            __half2 h23 = __floats2half2_rn(v2, v3);
            float2 hf01 = __half22float2(h01);
            float2 hf23 = __half22float2(h23);
            __half2 l01 = __floats2half2_rn(v0 - hf01.x, v1 - hf01.y);
            __half2 l23 = __floats2half2_rn(v2 - hf23.x, v3 - hf23.y);
            *(u32*)(a_hi + rlo * 264 + c) = *(u32*)&h01;
            *(u32*)(a_hi + rhi * 264 + c) = *(u32*)&h23;
            *(u32*)(a_lo + rlo * 264 + c) = *(u32*)&l01;
            *(u32*)(a_lo + rhi * 264 + c) = *(u32*)&l23;
        }
}

// gate GEMM2 epilogue: h2 = acc + bias (fp32, stride 260, no relu); M=32
__device__ __forceinline__ void epi_h2(const float (&acc)[2][4][4],
                                       const float* __restrict__ bias,
                                       float* h2, int tid) {
    const int lane = tid & 31, wid = tid >> 5;
    const int n_off = wid * 32;
    const int g = lane >> 2, tt = lane & 3;
#pragma unroll
    for (int im = 0; im < 2; im++)
#pragma unroll
        for (int j = 0; j < 4; j++) {
            const int c = n_off + j * 8 + 2 * tt;
            const float b0 = bias[c], b1 = bias[c + 1];
            const int rlo = im * 16 + g, rhi = rlo + 8;
            h2[rlo * 260 + c]     = acc[im][j][0] + b0;
            h2[rlo * 260 + c + 1] = acc[im][j][1] + b1;
            h2[rhi * 260 + c]     = acc[im][j][2] + b0;
            h2[rhi * 260 + c + 1] = acc[im][j][3] + b1;
        }
}

// ---------------- kernel 0: prep (reset + convert expert + gate weights) ------
__global__ void prep_kernel(
    const float* __restrict__ gw1, const float* __restrict__ gw2,
    const float* __restrict__ ew0, const float* __restrict__ ew1,
    const float* __restrict__ ew2, const float* __restrict__ ew3,
    const float* __restrict__ ew4, const float* __restrict__ ew5,
    const float* __restrict__ ew6) {
    int b = blockIdx.x;
    if (b == 0 && threadIdx.x < NE) g_count[threadIdx.x] = 0;
    if (b < NE * WROWS) {
        int idx = b * 256 + threadIdx.x;
        int e   = idx / (WROWS * 256);
        int rem = idx - e * (WROWS * 256);
        int r = rem >> 8, n = rem & 255;
        float w = 0.f;
        if (r < 96) {                       // L0, permuted [latent|x|pad]
            if (r < 32)      w = ew0[((size_t)e * 95 + 63 + r) * 256 + n];
            else if (r < 95) w = ew0[((size_t)e * 95 + (r - 32)) * 256 + n];
        }
        else if (r < 352)  w = ew1[((size_t)e * 256 + (r - 96)) * 256 + n];
        else if (r < 608)  w = ew2[((size_t)e * 256 + (r - 352)) * 256 + n];
        else if (r < 864)  w = ew3[((size_t)e * 256 + (r - 608)) * 256 + n];
        else if (r < 1120) w = ew4[((size_t)e * 256 + (r - 864)) * 256 + n];
        else if (r < 1376) w = ew5[((size_t)e * 351 + (r - 1120)) * 256 + n];
        else if (r < 1472) {                // L5 h0-part, permuted
            int rp = r - 1376;
            if (rp < 32)      w = ew5[((size_t)e * 351 + 319 + rp) * 256 + n];
            else if (rp < 95) w = ew5[((size_t)e * 351 + 224 + rp) * 256 + n];
        }
        else               w = ew6[((size_t)e * 256 + (r - 1472)) * 256 + n];
        split2h(w, g_wh[idx], g_wl[idx]);
    } else {
        int idx = (b - NE * WROWS) * 256 + threadIdx.x;   // < GWROWS*256
        int r = idx >> 8, n = idx & 255;
        float w = 0.f;
        if (r < 256)      w = gw1[(size_t)(63 + r) * 256 + n];   // sl rows
        else if (r < 319) w = gw1[(size_t)(r - 256) * 256 + n];  // x rows
        else if (r >= 320) w = gw2[(size_t)(r - 320) * 256 + n];
        split2h(w, g_gh[idx], g_gl[idx]);
    }
}

// ---------------- kernel 1: gate network + routing (TC fp16-split, M=32) ------
// smem bytes: region0 [0, 41984): gi planes (2 x 32x328 u16) -> a planes
//             (2 x 32x264 u16) -> h2 fp32 (32x260) ; lgbuf at 33792
//             wst at 41984: 2 x 16896 B; gw3t aliases wst after GEMMs
#define GATE_SMEM_B (41984 + 33792)

__global__ __launch_bounds__(NT, 2) void gate_kernel(
    const float* __restrict__ x,  const float* __restrict__ sl,
    const float* __restrict__ gb1, const float* __restrict__ gb2,
    const float* __restrict__ lng, const float* __restrict__ lnb,
    const float* __restrict__ gw3, const float* __restrict__ gb3) {
    extern __shared__ u16 smu[];
    u16* gi_hi = smu;                       // 32*328
    u16* gi_lo = smu + 10496;
    u16* a_hi  = smu;                       // 32*264 (after GEMM1)
    u16* a_lo  = smu + 8448;
    float* h2    = (float*)smu;             // 32*260 (after GEMM2)
    float* lgbuf = (float*)((char*)smu + 33792);   // 32*8
    float* gw3t  = (float*)((char*)smu + 41984);   // 8*256 (aliases wst)
    const u32 wstu = (u32)__cvta_generic_to_shared((char*)smu + 41984);

    const int tid = threadIdx.x;
    const int row0 = blockIdx.x * MR;
    const int lane = tid & 31, wid = tid >> 5;
    const int n_off = wid * 32;
    const u32 bboff = (u32)(((lane & 15) * 264 + n_off + (lane >> 4) * 8) * 2);

    // gather g_in (cols: [sl 0..255 | x 256..318 | pad]) split into fp16 planes
#pragma unroll
    for (int i = 0; i < 8; i++) {          // sl part: float4 loads (2048 total)
        int t = tid + i * NT;
        int r = t >> 6, j = (t & 63) * 4;
        float4 v = *(const float4*)(sl + (size_t)(row0 + r) * 256 + j);
        split4_store(v, gi_hi + r * 328 + j, gi_lo + r * 328 + j);
    }
#pragma unroll
    for (int i = 0; i < 8; i++) {          // x part + col-319 pad (2048 total)
        int t = tid + i * NT;
        int r = t >> 6, c = t & 63;
        float v = (c < 63) ? x[(size_t)(row0 + r) * 63 + c] : 0.f;
        split2h(v, gi_hi[r * 328 + 256 + c], gi_lo[r * 328 + 256 + c]);
    }
    {                                       // pad cols 320..327 (256 total)
        int r = tid >> 3, c = 320 + (tid & 7);
        gi_hi[r * 328 + c] = 0; gi_lo[r * 328 + c] = 0;
    }
    __syncthreads();

    const u32 gihi_b = (u32)__cvta_generic_to_shared(gi_hi)
                     + (u32)((lane & 15) * 656) + (u32)((lane >> 4) * 16);
    const u32 gilo_b = (u32)__cvta_generic_to_shared(gi_lo)
                     + (u32)((lane & 15) * 656) + (u32)((lane >> 4) * 16);
    const u32 ahi_b = (u32)__cvta_generic_to_shared(a_hi)
                    + (u32)((lane & 15) * 528) + (u32)((lane >> 4) * 16);
    const u32 alo_b = (u32)__cvta_generic_to_shared(a_lo)
                    + (u32)((lane & 15) * 528) + (u32)((lane >> 4) * 16);

    float acc[2][4][4];

    // GEMM1: g_in (K=320) @ gw1 -> relu -> h1 split planes  (20 x 16-row chunks)
    zero_acc_tc(acc);
    gemm_tc3(acc, gihi_b, gilo_b, 656, g_gh, g_gl, 20, wstu, bboff, tid);
    __syncthreads();
    epi_relu(acc, gb1, a_hi, a_lo, tid);
    __syncthreads();

    // GEMM2: h1 (K=256) @ gw2 -> h2 fp32  (16 x 16-row chunks)
    zero_acc_tc(acc);
    gemm_tc3(acc, ahi_b, alo_b, 528, g_gh + 320 * 256, g_gl + 320 * 256,
             16, wstu, bboff, tid);
    __syncthreads();
    epi_h2(acc, gb2, h2, tid);
    __syncthreads();

    // LayerNorm per row: 8 threads/row (32 rows), two-pass (stride 260)
    {
        int r = tid >> 3, sub = tid & 7;
        float* h2r = h2 + r * 260;
        float s = 0.f;
#pragma unroll 8
        for (int k = 0; k < 32; k++) s += h2r[sub + 8 * k];
        s += __shfl_xor_sync(0xffffffffu, s, 1);
        s += __shfl_xor_sync(0xffffffffu, s, 2);
        s += __shfl_xor_sync(0xffffffffu, s, 4);
        float mu = s * (1.f / 256.f);
        float vv = 0.f;
#pragma unroll 8
        for (int k = 0; k < 32; k++) {
            float d = h2r[sub + 8 * k] - mu;
            vv += d * d;
        }
        vv += __shfl_xor_sync(0xffffffffu, vv, 1);
        vv += __shfl_xor_sync(0xffffffffu, vv, 2);
        vv += __shfl_xor_sync(0xffffffffu, vv, 4);
        float rstd = rsqrtf(vv * (1.f / 256.f) + 1e-5f);
#pragma unroll 8
        for (int k = 0; k < 32; k++) {
            int c = sub + 8 * k;
            float nv = (h2r[c] - mu) * rstd;
            h2r[c] = nv * lng[c] + lnb[c];
        }
    }
    // stage gw3 transposed [e][k] into (now idle) wst region
    for (int i = tid; i < 2048; i += NT) {
        int e = i >> 8, k = i & 255;
        gw3t[i] = gw3[k * 8 + e];
    }
    __syncthreads();

    // logits = h2 @ gw3 + gb3 (float4 LDS; one task per thread, 32x8)
    {
        int r = tid >> 3, e = tid & 7;
        float d = gb3[e];
        const float4* h4 = (const float4*)(h2 + r * 260);
        const float4* w4 = (const float4*)(gw3t + e * 256);
#pragma unroll 8
        for (int k = 0; k < 64; k++) {
            float4 a = h4[k], w = w4[k];
            d += a.x * w.x; d += a.y * w.y; d += a.z * w.z; d += a.w * w.w;
        }
        lgbuf[r * 8 + e] = d;
    }
    __syncthreads();

    // softmax / argmax / append to expert list
    if (tid < MR) {
        int gi = row0 + tid;
        const float* lg = lgbuf + tid * 8;
        float best = lg[0];
        int bi = 0;
#pragma unroll
        for (int e = 1; e < 8; e++) {
            float v = lg[e];
            if (v > best) { best = v; bi = e; }
        }
        float ssum = 0.f;
#pragma unroll
        for (int e = 0; e < 8; e++) ssum += expf(lg[e] - best);
        g_gv[gi] = 1.f / ssum;
        int pos = atomicAdd(&g_count[bi], 1);
        g_list[bi][pos] = gi;
    }
}

// ---------------- kernel 2: routed expert MLP (TC, cp.async staged, M=32) -----
// smem: a_hi 16896B | a_lo 16896B | h_hi 6656B | h_lo 6656B | wst 33792B
#define EXP_SMEM_B (16896 * 2 + 6656 * 2 + 33792)
#define EXP_TILES  (BPTS / MR + NE)

__global__ __launch_bounds__(NT, 2) void expert_kernel(
    const float* __restrict__ x,  const float* __restrict__ sl,
    const float* __restrict__ eb0, const float* __restrict__ eb1,
    const float* __restrict__ eb2, const float* __restrict__ eb3,
    const float* __restrict__ eb4, const float* __restrict__ eb5,
    const float* __restrict__ eb6,
    const float* __restrict__ ewo, const float* __restrict__ ebo,
    float* __restrict__ out) {
    int t = blockIdx.x;
    int e, base = 0, n = 0;
    for (e = 0; e < NE; e++) {
        n = g_count[e];
        int T = (n + MR - 1) / MR;
        if (t < base + T) break;
        base += T;
    }
    if (e == NE) return;
    const int start = (t - base) * MR;
    const int nrows = min(MR, n - start);

    extern __shared__ u16 smu[];
    u16* a_hi = smu;                    // 32*264
    u16* a_lo = smu + 8448;
    u16* h_hi = smu + 2 * 8448;         // 32*104
    u16* h_lo = h_hi + 3328;
    u16* wst  = smu + 2 * 8448 + 2 * 3328;
    __shared__ int ridx[MR];
    const int tid = threadIdx.x;
    const int lane = tid & 31, wid = tid >> 5;
    const int n_off = wid * 32;

    if (tid < MR) ridx[tid] = (tid < nrows) ? g_list[e][start + tid] : -1;
    __syncthreads();

    // gather h0 (cols: [latent 0..31 | x 32..94 | pad]) split into fp16 planes
    {                                   // latent part: float4 loads, 1/thread
        int r = tid >> 3, j = (tid & 7) * 4;
        int gi = ridx[r];
        float4 v = make_float4(0.f, 0.f, 0.f, 0.f);
        if (gi >= 0) v = *(const float4*)(sl + (size_t)gi * 256 + e * CHUNKD + j);
        split4_store(v, h_hi + r * 104 + j, h_lo + r * 104 + j);
    }
#pragma unroll
    for (int i = 0; i < 8; i++) {       // x part + col-95 pad (2048 total)
        int t2 = tid + i * NT;
        int r = t2 >> 6, c = t2 & 63;
        int gi = ridx[r];
        float v = (c < 63 && gi >= 0) ? x[(size_t)gi * 63 + c] : 0.f;
        split2h(v, h_hi[r * 104 + 32 + c], h_lo[r * 104 + 32 + c]);
    }
    __syncthreads();

    const u32 a_hi_b = (u32)__cvta_generic_to_shared(a_hi)
                     + (u32)((lane & 15) * 528) + (u32)((lane >> 4) * 16);
    const u32 a_lo_b = (u32)__cvta_generic_to_shared(a_lo)
                     + (u32)((lane & 15) * 528) + (u32)((lane >> 4) * 16);
    const u32 h_hi_b = (u32)__cvta_generic_to_shared(h_hi)
                     + (u32)((lane & 15) * 208) + (u32)((lane >> 4) * 16);
    const u32 h_lo_b = (u32)__cvta_generic_to_shared(h_lo)
                     + (u32)((lane & 15) * 208) + (u32)((lane >> 4) * 16);
    const u32 wstu = (u32)__cvta_generic_to_shared(wst);
    const u32 bboff = (u32)(((lane & 15) * 264 + n_off + (lane >> 4) * 8) * 2);

    const u16* WH = g_wh + (size_t)e * WROWS * 256;
    const u16* WL = g_wl + (size_t)e * WROWS * 256;
    float acc[2][4][4];

    // L0: h0 (K=96) -> 256  (6 x 16-row chunks)
    zero_acc_tc(acc);
    gemm_tc3(acc, h_hi_b, h_lo_b, 208, WH, WL, 6, wstu, bboff, tid);
    __syncthreads();
    epi_relu(acc, eb0 + e * 256, a_hi, a_lo, tid);
    __syncthreads();

    // L1..L4: 256 -> 256  (16 x 16-row chunks each)
    const float* bl4[4] = { eb1, eb2, eb3, eb4 };
#pragma unroll 1
    for (int l = 0; l < 4; l++) {
        zero_acc_tc(acc);
        gemm_tc3(acc, a_hi_b, a_lo_b, 528,
                 WH + (size_t)(96 + l * 256) * 256, WL + (size_t)(96 + l * 256) * 256,
                 16, wstu, bboff, tid);
        __syncthreads();
        epi_relu(acc, bl4[l] + e * 256, a_hi, a_lo, tid);
        __syncthreads();
    }

    // L5 (skip): act part (K=256) + h0 part (K=96)
    zero_acc_tc(acc);
    gemm_tc3(acc, a_hi_b, a_lo_b, 528,
             WH + (size_t)1120 * 256, WL + (size_t)1120 * 256, 16, wstu, bboff, tid);
    gemm_tc3(acc, h_hi_b, h_lo_b, 208,
             WH + (size_t)1376 * 256, WL + (size_t)1376 * 256, 6, wstu, bboff, tid);
    __syncthreads();
    epi_relu(acc, eb5 + e * 256, a_hi, a_lo, tid);
    __syncthreads();

    // L6
    zero_acc_tc(acc);
    gemm_tc3(acc, a_hi_b, a_lo_b, 528,
             WH + (size_t)1472 * 256, WL + (size_t)1472 * 256, 16, wstu, bboff, tid);
    __syncthreads();
    epi_relu(acc, eb6 + e * 256, a_hi, a_lo, tid);
    __syncthreads();

    // output head: y = act @ ewo[e] + ebo[e]; combine with gate (32x4 tasks)
    if (tid < MR * 4) {
        int r = tid >> 2, o = tid & 3;
        if (r < nrows) {
            float d = ebo[e * 4 + o];
            const float* wo = ewo + (size_t)e * 1024 + o;
            const __half2* ah2 = (const __half2*)(a_hi + r * 264);
            const __half2* al2 = (const __half2*)(a_lo + r * 264);
#pragma unroll 8
            for (int k = 0; k < 128; k++) {
                float2 hv = __half22float2(ah2[k]);
                float2 lv = __half22float2(al2[k]);
                d += (hv.x + lv.x) * wo[(2 * k) * 4];
                d += (hv.y + lv.y) * wo[(2 * k + 1) * 4];
            }
            int gi = ridx[r];
            float comb = g_gv[gi] * expf(d);
            if (comb == 0.f) comb = EPSF;
            out[gi * 4 + o] = logf(comb);
        }
    }
}

// ---------------- launch -----------------------------------------------------
extern "C" void kernel_launch(void* const* d_in, const int* in_sizes, int n_in,
                              void* d_out, int out_size) {
    const float* x   = (const float*)d_in[0];
    const float* sl  = (const float*)d_in[1];
    const float* gw1 = (const float*)d_in[2];
    const float* gb1 = (const float*)d_in[3];
    const float* gw2 = (const float*)d_in[4];
    const float* gb2 = (const float*)d_in[5];
    const float* lng = (const float*)d_in[6];
    const float* lnb = (const float*)d_in[7];
    const float* gw3 = (const float*)d_in[8];
    const float* gb3 = (const float*)d_in[9];
    const float* ew0 = (const float*)d_in[10];
    const float* eb0 = (const float*)d_in[11];
    const float* ew1 = (const float*)d_in[12];
    const float* eb1 = (const float*)d_in[13];
    const float* ew2 = (const float*)d_in[14];
    const float* eb2 = (const float*)d_in[15];
    const float* ew3 = (const float*)d_in[16];
    const float* eb3 = (const float*)d_in[17];
    const float* ew4 = (const float*)d_in[18];
    const float* eb4 = (const float*)d_in[19];
    const float* ew5 = (const float*)d_in[20];
    const float* eb5 = (const float*)d_in[21];
    const float* ew6 = (const float*)d_in[22];
    const float* eb6 = (const float*)d_in[23];
    const float* ewo = (const float*)d_in[24];
    const float* ebo = (const float*)d_in[25];
    float* out = (float*)d_out;

    cudaFuncSetAttribute(gate_kernel, cudaFuncAttributeMaxDynamicSharedMemorySize,
                         GATE_SMEM_B);
    cudaFuncSetAttribute(expert_kernel, cudaFuncAttributeMaxDynamicSharedMemorySize,
                         EXP_SMEM_B);

    prep_kernel<<<NE * WROWS + GWROWS, 256>>>(gw1, gw2, ew0, ew1, ew2, ew3,
                                              ew4, ew5, ew6);
    gate_kernel<<<BPTS / MR, NT, GATE_SMEM_B>>>(x, sl, gb1, gb2,
                                                lng, lnb, gw3, gb3);
    expert_kernel<<<EXP_TILES, NT, EXP_SMEM_B>>>(
        x, sl, eb0, eb1, eb2, eb3, eb4, eb5, eb6, ewo, ebo, out);
}

// round 13
// speedup vs baseline: 1.0226x; 1.0226x over previous
#include <cuda_runtime.h>
#include <cuda_fp16.h>

#define BPTS   16384
#define NE     8
#define CHUNKD 32
#define EPSF   2.220446049250313e-16f
#define WROWS  1728           // padded expert K rows: 96+4*256+256+96+256
#define GWROWS 576            // gate: 320 (gw1 padded) + 256 (gw2)
#define NT     512
typedef unsigned int u32;
typedef unsigned short u16;

// ---------------- scratch (static device globals) ----------------------------
__device__ int   g_count[NE];
__device__ int   g_list[NE][BPTS];
__device__ float g_gv[BPTS];
// expert weights row-major [e][k][n(256)] fp16 hi / lo
__device__ u16 g_wh[NE * WROWS * 256];
__device__ u16 g_wl[NE * WROWS * 256];
// gate weights [k(576)][n(256)] fp16 hi / lo
__device__ u16 g_gh[GWROWS * 256];
__device__ u16 g_gl[GWROWS * 256];

// ---------------- tensor-core helpers ----------------------------------------
__device__ __forceinline__ void mma_f16(float d[4], u32 a0, u32 a1, u32 a2, u32 a3,
                                        u32 b0, u32 b1) {
    asm volatile(
        "mma.sync.aligned.m16n8k16.row.col.f32.f16.f16.f32 "
        "{%0,%1,%2,%3}, {%4,%5,%6,%7}, {%8,%9}, {%0,%1,%2,%3};"
        : "+f"(d[0]), "+f"(d[1]), "+f"(d[2]), "+f"(d[3])
        : "r"(a0), "r"(a1), "r"(a2), "r"(a3), "r"(b0), "r"(b1));
}
__device__ __forceinline__ void ldsm4(u32 r[4], u32 addr) {
    asm volatile("ldmatrix.sync.aligned.m8n8.x4.shared.b16 {%0,%1,%2,%3}, [%4];"
                 : "=r"(r[0]), "=r"(r[1]), "=r"(r[2]), "=r"(r[3]) : "r"(addr));
}
__device__ __forceinline__ void ldsm4t(u32 r[4], u32 addr) {
    asm volatile("ldmatrix.sync.aligned.m8n8.x4.trans.shared.b16 {%0,%1,%2,%3}, [%4];"
                 : "=r"(r[0]), "=r"(r[1]), "=r"(r[2]), "=r"(r[3]) : "r"(addr));
}
#define CP16(dst, src) \
    asm volatile("cp.async.cg.shared.global [%0], [%1], 16;" :: "r"(dst), "l"(src))
#define CPCOMMIT() asm volatile("cp.async.commit_group;")
#define CPWAIT0()  asm volatile("cp.async.wait_group 0;")
#define CPWAIT1()  asm volatile("cp.async.wait_group 1;")

__device__ __forceinline__ void split2h(float v, u16& h, u16& l) {
    __half hh = __float2half_rn(v);
    __half ll = __float2half_rn(v - __half2float(hh));
    h = *(u16*)&hh;  l = *(u16*)&ll;
}

// ---------------- weight chunk staging (32 k-rows, hi+lo) ---------------------
// smem plane rows stride 264 u16 (528 B); lo plane at +16896 B. Buffer 33792 B.
__device__ __forceinline__ void stage_chunk32(
    u32 dst_base, const u16* __restrict__ Wh, const u16* __restrict__ Wl,
    int c, int tid) {
#pragma unroll
    for (int p = 0; p < 4; p++) {
        int uu = tid + p * NT;
        int isLo = uu >> 10;
        int v = uu & 1023;
        int row = v >> 5, col = v & 31;
        const u16* src = (isLo ? Wl : Wh) + (size_t)(c * 32 + row) * 256 + col * 8;
        u32 dst = dst_base + isLo * 16896 + row * 528 + col * 16;
        CP16(dst, src);
    }
}

// GEMM: acc[64x256] += A[64xK] @ W[Kx256]; A pre-split fp16 hi/lo planes in
// smem (ldmatrix), W staged hi/lo via cp.async, 3-stage ring of 32-row chunks.
// 16 warps: warp grid 2(M=32) x 8(N=32); acc[2][4][4] per thread.
// Entry barrier: all warps must be done with prior use of the wst buffers
// before the prologue overwrites them (back-to-back gemm calls share wst).
__device__ __forceinline__ void gemm_tc3(
    float (&acc)[2][4][4],
    u32 a_hi_b, u32 a_lo_b, int rowbytes,
    const u16* __restrict__ Wh, const u16* __restrict__ Wl,
    int nc, u32 wstu, u32 bboff, int tid)
{
    __syncthreads();                   // protect wst ring from previous gemm
    stage_chunk32(wstu, Wh, Wl, 0, tid);
    CPCOMMIT();
    if (nc > 1) {
        stage_chunk32(wstu + 33792, Wh, Wl, 1, tid);
        CPCOMMIT();
    }
    u32 ah[2][4], al[2][4], bh[4], bl[4];
    int buf = 0;                       // buffer index of chunk c (mod 3)
    for (int c = 0; c < nc; c++) {
        if (c + 1 < nc) { CPWAIT1(); } else { CPWAIT0(); }
        __syncthreads();
        if (c + 2 < nc) {
            int nb3 = buf + 2; if (nb3 >= 3) nb3 -= 3;
            stage_chunk32(wstu + nb3 * 33792, Wh, Wl, c + 2, tid);
            CPCOMMIT();
        }
        const u32 cur = wstu + buf * 33792;
#pragma unroll
        for (int ks = 0; ks < 2; ks++) {
            const u32 aoff = (u32)(c * 64 + ks * 32);
            ldsm4(ah[0], a_hi_b + aoff);
            ldsm4(ah[1], a_hi_b + 16 * rowbytes + aoff);
            ldsm4(al[0], a_lo_b + aoff);
            ldsm4(al[1], a_lo_b + 16 * rowbytes + aoff);
            const u32 bb = cur + bboff + ks * 8448;
#pragma unroll
            for (int gg = 0; gg < 2; gg++) {
                ldsm4t(bh, bb + gg * 32);
                ldsm4t(bl, bb + 16896 + gg * 32);
#pragma unroll
                for (int nb = 0; nb < 2; nb++) {
                    const int j = gg * 2 + nb;
                    const u32 b0 = bh[2 * nb], b1 = bh[2 * nb + 1];
                    const u32 c0 = bl[2 * nb], c1 = bl[2 * nb + 1];
#pragma unroll
                    for (int im = 0; im < 2; im++) {
                        mma_f16(acc[im][j], ah[im][0], ah[im][1], ah[im][2], ah[im][3], b0, b1);
                        mma_f16(acc[im][j], al[im][0], al[im][1], al[im][2], al[im][3], b0, b1);
                        mma_f16(acc[im][j], ah[im][0], ah[im][1], ah[im][2], ah[im][3], c0, c1);
                    }
                }
            }
        }
        if (++buf == 3) buf = 0;
    }
}

__device__ __forceinline__ void zero_acc_tc(float (&acc)[2][4][4]) {
#pragma unroll
    for (int im = 0; im < 2; im++)
#pragma unroll
        for (int j = 0; j < 4; j++)
#pragma unroll
            for (int q = 0; q < 4; q++) acc[im][j][q] = 0.f;
}

// epilogue: relu(acc+bias) -> split fp16 hi/lo planes (stride 264)
__device__ __forceinline__ void epi_relu(const float (&acc)[2][4][4],
                                         const float* __restrict__ bias,
                                         u16* a_hi, u16* a_lo, int tid) {
    const int lane = tid & 31, wid = tid >> 5;
    const int m0 = (wid & 1) * 32, n_off = (wid >> 1) * 32;
    const int g = lane >> 2, tt = lane & 3;
#pragma unroll
    for (int im = 0; im < 2; im++)
#pragma unroll
        for (int j = 0; j < 4; j++) {
            const int c = n_off + j * 8 + 2 * tt;
            const float b0 = bias[c], b1 = bias[c + 1];
            const int rlo = m0 + im * 16 + g, rhi = rlo + 8;
            float v0 = fmaxf(acc[im][j][0] + b0, 0.f);
            float v1 = fmaxf(acc[im][j][1] + b1, 0.f);
            float v2 = fmaxf(acc[im][j][2] + b0, 0.f);
            float v3 = fmaxf(acc[im][j][3] + b1, 0.f);
            __half2 h01 = __floats2half2_rn(v0, v1);
            __half2 h23 = __floats2half2_rn(v2, v3);
            float2 hf01 = __half22float2(h01);
            float2 hf23 = __half22float2(h23);
            __half2 l01 = __floats2half2_rn(v0 - hf01.x, v1 - hf01.y);
            __half2 l23 = __floats2half2_rn(v2 - hf23.x, v3 - hf23.y);
            *(u32*)(a_hi + rlo * 264 + c) = *(u32*)&h01;
            *(u32*)(a_hi + rhi * 264 + c) = *(u32*)&h23;
            *(u32*)(a_lo + rlo * 264 + c) = *(u32*)&l01;
            *(u32*)(a_lo + rhi * 264 + c) = *(u32*)&l23;
        }
}

// gate GEMM2 epilogue: h2 = acc + bias (fp32, stride 257, no relu)
__device__ __forceinline__ void epi_h2(const float (&acc)[2][4][4],
                                       const float* __restrict__ bias,
                                       float* h2, int tid) {
    const int lane = tid & 31, wid = tid >> 5;
    const int m0 = (wid & 1) * 32, n_off = (wid >> 1) * 32;
    const int g = lane >> 2, tt = lane & 3;
#pragma unroll
    for (int im = 0; im < 2; im++)
#pragma unroll
        for (int j = 0; j < 4; j++) {
            const int c = n_off + j * 8 + 2 * tt;
            const float b0 = bias[c], b1 = bias[c + 1];
            const int rlo = m0 + im * 16 + g, rhi = rlo + 8;
            h2[rlo * 257 + c]     = acc[im][j][0] + b0;
            h2[rlo * 257 + c + 1] = acc[im][j][1] + b1;
            h2[rhi * 257 + c]     = acc[im][j][2] + b0;
            h2[rhi * 257 + c + 1] = acc[im][j][3] + b1;
        }
}

// ---------------- kernel 0: reset ---------------------------------------------
__global__ void reset_kernel() {
    if (threadIdx.x < NE) g_count[threadIdx.x] = 0;
}

// ---------------- kernel 0b: split expert weights to fp16 hi/lo ----------------
__global__ void convert_weights(
    const float* __restrict__ ew0, const float* __restrict__ ew1,
    const float* __restrict__ ew2, const float* __restrict__ ew3,
    const float* __restrict__ ew4, const float* __restrict__ ew5,
    const float* __restrict__ ew6) {
    int idx = blockIdx.x * 256 + threadIdx.x;          // < NE*WROWS*256
    int e   = idx / (WROWS * 256);
    int rem = idx - e * (WROWS * 256);
    int r = rem >> 8, n = rem & 255;
    float w = 0.f;
    if (r < 96)        { int k = r;            if (k < 95) w = ew0[((size_t)e * 95 + k) * 256 + n]; }
    else if (r < 352)  { int k = r - 96;       w = ew1[((size_t)e * 256 + k) * 256 + n]; }
    else if (r < 608)  { int k = r - 352;      w = ew2[((size_t)e * 256 + k) * 256 + n]; }
    else if (r < 864)  { int k = r - 608;      w = ew3[((size_t)e * 256 + k) * 256 + n]; }
    else if (r < 1120) { int k = r - 864;      w = ew4[((size_t)e * 256 + k) * 256 + n]; }
    else if (r < 1376) { int k = r - 1120;     w = ew5[((size_t)e * 351 + k) * 256 + n]; }
    else if (r < 1472) { int k = 256 + (r - 1376); if (k < 351) w = ew5[((size_t)e * 351 + k) * 256 + n]; }
    else               { int k = r - 1472;     w = ew6[((size_t)e * 256 + k) * 256 + n]; }
    split2h(w, g_wh[idx], g_wl[idx]);
}

// ---------------- kernel 0c: split gate weights --------------------------------
__global__ void convert_gate_weights(const float* __restrict__ gw1,
                                     const float* __restrict__ gw2) {
    int idx = blockIdx.x * 256 + threadIdx.x;          // < GWROWS*256
    int r = idx >> 8, n = idx & 255;
    float w = 0.f;
    if (r < 320) { if (r < 319) w = gw1[(size_t)r * 256 + n]; }
    else         w = gw2[(size_t)(r - 320) * 256 + n];
    split2h(w, g_gh[idx], g_gl[idx]);
}

// ---------------- kernel 1: gate network + routing (TC fp16-split) -------------
// smem bytes: region0 [0, 84992): gi planes (2 x 64x328 u16) -> h1 planes
//             (2 x 64x264 u16) -> h2 fp32 (64x257) + logits (at 66048)
//             wst at 84992: 3 x 33792 B
#define GATE_SMEM_B (84992 + 101376)

__global__ __launch_bounds__(NT, 1) void gate_kernel(
    const float* __restrict__ x,  const float* __restrict__ sl,
    const float* __restrict__ gb1, const float* __restrict__ gb2,
    const float* __restrict__ lng, const float* __restrict__ lnb,
    const float* __restrict__ gw3, const float* __restrict__ gb3) {
    extern __shared__ u16 smu[];
    u16* gi_hi = smu;                       // 64*328
    u16* gi_lo = smu + 20992;
    u16* a_hi  = smu;                       // 64*264 (after GEMM1)
    u16* a_lo  = smu + 16896;
    float* h2    = (float*)smu;             // 64*257 (after GEMM2)
    float* lgbuf = (float*)((char*)smu + 66048);   // 64*8
    const u32 wstu = (u32)__cvta_generic_to_shared((char*)smu + 84992);

    const int tid = threadIdx.x;
    const int row0 = blockIdx.x * 64;
    const int lane = tid & 31, wid = tid >> 5;
    const int m0 = (wid & 1) * 32, n_off = (wid >> 1) * 32;
    const u32 bboff = (u32)(((lane & 15) * 264 + n_off + (lane >> 4) * 8) * 2);

    // gather g_in = concat(x, shape_latent) split into fp16 hi/lo (stride 328)
    for (int idx = tid; idx < 64 * 328; idx += NT) {
        int r = idx / 328, c = idx - r * 328;
        int gi = row0 + r;
        float v = 0.f;
        if (c < 63)       v = x[gi * 63 + c];
        else if (c < 319) v = sl[gi * 256 + (c - 63)];
        split2h(v, gi_hi[idx], gi_lo[idx]);
    }

    const u32 gihi_b = (u32)__cvta_generic_to_shared(gi_hi)
                     + (u32)((m0 + (lane & 15)) * 656) + (u32)((lane >> 4) * 16);
    const u32 gilo_b = (u32)__cvta_generic_to_shared(gi_lo)
                     + (u32)((m0 + (lane & 15)) * 656) + (u32)((lane >> 4) * 16);
    const u32 ahi_b = (u32)__cvta_generic_to_shared(a_hi)
                    + (u32)((m0 + (lane & 15)) * 528) + (u32)((lane >> 4) * 16);
    const u32 alo_b = (u32)__cvta_generic_to_shared(a_lo)
                    + (u32)((m0 + (lane & 15)) * 528) + (u32)((lane >> 4) * 16);

    float acc[2][4][4];

    // GEMM1: g_in (K=320) @ gw1 -> relu -> h1 split planes  (10 x 32-row chunks)
    zero_acc_tc(acc);
    gemm_tc3(acc, gihi_b, gilo_b, 656, g_gh, g_gl, 10, wstu, bboff, tid);
    __syncthreads();
    epi_relu(acc, gb1, a_hi, a_lo, tid);

    // GEMM2: h1 (K=256) @ gw2 -> h2 fp32  (8 x 32-row chunks)
    zero_acc_tc(acc);
    gemm_tc3(acc, ahi_b, alo_b, 528, g_gh + 320 * 256, g_gl + 320 * 256,
             8, wstu, bboff, tid);
    __syncthreads();
    epi_h2(acc, gb2, h2, tid);
    __syncthreads();

    // LayerNorm per row: 8 threads/row, two-pass
    {
        int r = tid >> 3, sub = tid & 7;
        float* h2r = h2 + r * 257;
        float s = 0.f;
#pragma unroll 8
        for (int k = 0; k < 32; k++) s += h2r[sub + 8 * k];
        s += __shfl_xor_sync(0xffffffffu, s, 1);
        s += __shfl_xor_sync(0xffffffffu, s, 2);
        s += __shfl_xor_sync(0xffffffffu, s, 4);
        float mu = s * (1.f / 256.f);
        float vv = 0.f;
#pragma unroll 8
        for (int k = 0; k < 32; k++) {
            float d = h2r[sub + 8 * k] - mu;
            vv += d * d;
        }
        vv += __shfl_xor_sync(0xffffffffu, vv, 1);
        vv += __shfl_xor_sync(0xffffffffu, vv, 2);
        vv += __shfl_xor_sync(0xffffffffu, vv, 4);
        float rstd = rsqrtf(vv * (1.f / 256.f) + 1e-5f);
#pragma unroll 8
        for (int k = 0; k < 32; k++) {
            int c = sub + 8 * k;
            float nv = (h2r[c] - mu) * rstd;
            h2r[c] = nv * lng[c] + lnb[c];
        }
    }
    __syncthreads();

    // logits = h2 @ gw3 + gb3 (fp32 scalar; one task per thread)
    {
        int r = tid >> 3, e = tid & 7;
        float d = gb3[e];
        const float* h2r = h2 + r * 257;
#pragma unroll 8
        for (int k = 0; k < 256; k++) d += h2r[k] * gw3[k * 8 + e];
        lgbuf[r * 8 + e] = d;
    }
    __syncthreads();

    // softmax / argmax / append to expert list
    if (tid < 64) {
        int gi = row0 + tid;
        const float* lg = lgbuf + tid * 8;
        float best = lg[0];
        int bi = 0;
#pragma unroll
        for (int e = 1; e < 8; e++) {
            float v = lg[e];
            if (v > best) { best = v; bi = e; }
        }
        float ssum = 0.f;
#pragma unroll
        for (int e = 0; e < 8; e++) ssum += expf(lg[e] - best);
        g_gv[gi] = 1.f / ssum;
        int pos = atomicAdd(&g_count[bi], 1);
        g_list[bi][pos] = gi;
    }
}

// ---------------- kernel 2: routed expert MLP (TC, cp.async staged) -----------
// smem elems (u16): a_hi[16896] a_lo[16896] h_hi[6656] h_lo[6656] wst[3x16896]
#define EXP_SMEM_B ((16896 * 2 + 6656 * 2) * 2 + 101376)
#define EXP_TILES  (BPTS / 64 + NE)

__global__ __launch_bounds__(NT, 1) void expert_kernel(
    const float* __restrict__ x,  const float* __restrict__ sl,
    const float* __restrict__ eb0, const float* __restrict__ eb1,
    const float* __restrict__ eb2, const float* __restrict__ eb3,
    const float* __restrict__ eb4, const float* __restrict__ eb5,
    const float* __restrict__ eb6,
    const float* __restrict__ ewo, const float* __restrict__ ebo,
    float* __restrict__ out) {
    int t = blockIdx.x;
    int e, base = 0, n = 0;
    for (e = 0; e < NE; e++) {
        n = g_count[e];
        int T = (n + 63) >> 6;
        if (t < base + T) break;
        base += T;
    }
    if (e == NE) return;
    const int start = (t - base) * 64;
    const int nrows = min(64, n - start);

    extern __shared__ u16 smu[];
    u16* a_hi = smu;                    // 64*264
    u16* a_lo = smu + 16896;
    u16* h_hi = smu + 2 * 16896;        // 64*104
    u16* h_lo = h_hi + 6656;
    u16* wst  = smu + 2 * 16896 + 2 * 6656;
    __shared__ int ridx[64];
    const int tid = threadIdx.x;
    const int lane = tid & 31, wid = tid >> 5;
    const int m0 = (wid & 1) * 32, n_off = (wid >> 1) * 32;

    if (tid < 64) ridx[tid] = (tid < nrows) ? g_list[e][start + tid] : -1;
    __syncthreads();

    // gather h0 = concat(x, latent chunk e) split into fp16 hi/lo planes
    for (int idx = tid; idx < 64 * 104; idx += NT) {
        int r = idx / 104, c = idx - r * 104;
        int gi = ridx[r];
        float v = 0.f;
        if (gi >= 0) {
            if (c < 63)      v = x[gi * 63 + c];
            else if (c < 95) v = sl[gi * 256 + e * CHUNKD + (c - 63)];
        }
        split2h(v, h_hi[idx], h_lo[idx]);
    }

    const u32 a_hi_b = (u32)__cvta_generic_to_shared(a_hi)
                     + (u32)((m0 + (lane & 15)) * 528) + (u32)((lane >> 4) * 16);
    const u32 a_lo_b = (u32)__cvta_generic_to_shared(a_lo)
                     + (u32)((m0 + (lane & 15)) * 528) + (u32)((lane >> 4) * 16);
    const u32 h_hi_b = (u32)__cvta_generic_to_shared(h_hi)
                     + (u32)((m0 + (lane & 15)) * 208) + (u32)((lane >> 4) * 16);
    const u32 h_lo_b = (u32)__cvta_generic_to_shared(h_lo)
                     + (u32)((m0 + (lane & 15)) * 208) + (u32)((lane >> 4) * 16);
    const u32 wstu = (u32)__cvta_generic_to_shared(wst);
    const u32 bboff = (u32)(((lane & 15) * 264 + n_off + (lane >> 4) * 8) * 2);

    const u16* WH = g_wh + (size_t)e * WROWS * 256;
    const u16* WL = g_wl + (size_t)e * WROWS * 256;
    float acc[2][4][4];

    // L0: h0 (K=96) -> 256  (3 x 32-row chunks)
    zero_acc_tc(acc);
    gemm_tc3(acc, h_hi_b, h_lo_b, 208, WH, WL, 3, wstu, bboff, tid);
    __syncthreads();
    epi_relu(acc, eb0 + e * 256, a_hi, a_lo, tid);

    // L1..L4: 256 -> 256  (8 x 32-row chunks each)
    const float* bl4[4] = { eb1, eb2, eb3, eb4 };
#pragma unroll 1
    for (int l = 0; l < 4; l++) {
        zero_acc_tc(acc);
        gemm_tc3(acc, a_hi_b, a_lo_b, 528,
                 WH + (size_t)(96 + l * 256) * 256, WL + (size_t)(96 + l * 256) * 256,
                 8, wstu, bboff, tid);
        __syncthreads();
        epi_relu(acc, bl4[l] + e * 256, a_hi, a_lo, tid);
    }

    // L5 (skip): act part (K=256) + h0 part (K=96)
    zero_acc_tc(acc);
    gemm_tc3(acc, a_hi_b, a_lo_b, 528,
             WH + (size_t)1120 * 256, WL + (size_t)1120 * 256, 8, wstu, bboff, tid);
    gemm_tc3(acc, h_hi_b, h_lo_b, 208,
             WH + (size_t)1376 * 256, WL + (size_t)1376 * 256, 3, wstu, bboff, tid);
    __syncthreads();
    epi_relu(acc, eb5 + e * 256, a_hi, a_lo, tid);

    // L6
    zero_acc_tc(acc);
    gemm_tc3(acc, a_hi_b, a_lo_b, 528,
             WH + (size_t)1472 * 256, WL + (size_t)1472 * 256, 8, wstu, bboff, tid);
    __syncthreads();
    epi_relu(acc, eb6 + e * 256, a_hi, a_lo, tid);
    __syncthreads();

    // output head: y = act @ ewo[e] + ebo[e]; combine with gate
    if (tid < 256) {
        int r = tid >> 2, o = tid & 3;
        if (r < nrows) {
            float d = ebo[e * 4 + o];
            const float* wo = ewo + (size_t)e * 1024 + o;
            const __half2* ah2 = (const __half2*)(a_hi + r * 264);
            const __half2* al2 = (const __half2*)(a_lo + r * 264);
#pragma unroll 8
            for (int k = 0; k < 128; k++) {
                float2 hv = __half22float2(ah2[k]);
                float2 lv = __half22float2(al2[k]);
                d += (hv.x + lv.x) * wo[(2 * k) * 4];
                d += (hv.y + lv.y) * wo[(2 * k + 1) * 4];
            }
            int gi = ridx[r];
            float comb = g_gv[gi] * expf(d);
            if (comb == 0.f) comb = EPSF;
            out[gi * 4 + o] = logf(comb);
        }
    }
}

// ---------------- launch -----------------------------------------------------
extern "C" void kernel_launch(void* const* d_in, const int* in_sizes, int n_in,
                              void* d_out, int out_size) {
    const float* x   = (const float*)d_in[0];
    const float* sl  = (const float*)d_in[1];
    const float* gw1 = (const float*)d_in[2];
    const float* gb1 = (const float*)d_in[3];
    const float* gw2 = (const float*)d_in[4];
    const float* gb2 = (const float*)d_in[5];
    const float* lng = (const float*)d_in[6];
    const float* lnb = (const float*)d_in[7];
    const float* gw3 = (const float*)d_in[8];
    const float* gb3 = (const float*)d_in[9];
    const float* ew0 = (const float*)d_in[10];
    const float* eb0 = (const float*)d_in[11];
    const float* ew1 = (const float*)d_in[12];
    const float* eb1 = (const float*)d_in[13];
    const float* ew2 = (const float*)d_in[14];
    const float* eb2 = (const float*)d_in[15];
    const float* ew3 = (const float*)d_in[16];
    const float* eb3 = (const float*)d_in[17];
    const float* ew4 = (const float*)d_in[18];
    const float* eb4 = (const float*)d_in[19];
    const float* ew5 = (const float*)d_in[20];
    const float* eb5 = (const float*)d_in[21];
    const float* ew6 = (const float*)d_in[22];
    const float* eb6 = (const float*)d_in[23];
    const float* ewo = (const float*)d_in[24];
    const float* ebo = (const float*)d_in[25];
    float* out = (float*)d_out;

    cudaFuncSetAttribute(gate_kernel, cudaFuncAttributeMaxDynamicSharedMemorySize,
                         GATE_SMEM_B);
    cudaFuncSetAttribute(expert_kernel, cudaFuncAttributeMaxDynamicSharedMemorySize,
                         EXP_SMEM_B);

    reset_kernel<<<1, 32>>>();
    convert_weights<<<NE * WROWS, 256>>>(ew0, ew1, ew2, ew3, ew4, ew5, ew6);
    convert_gate_weights<<<GWROWS, 256>>>(gw1, gw2);
    gate_kernel<<<BPTS / 64, NT, GATE_SMEM_B>>>(x, sl, gb1, gb2,
                                                lng, lnb, gw3, gb3);
    expert_kernel<<<EXP_TILES, NT, EXP_SMEM_B>>>(
        x, sl, eb0, eb1, eb2, eb3, eb4, eb5, eb6, ewo, ebo, out);
}

// round 14
// speedup vs baseline: 1.0514x; 1.0281x over previous
#include <cuda_runtime.h>
#include <cuda_fp16.h>

#define BPTS   16384
#define NE     8
#define CHUNKD 32
#define EPSF   2.220446049250313e-16f
#define WROWS  1728           // padded expert K rows: 96+4*256+256+96+256
#define GWROWS 576            // gate: 320 (gw1 padded) + 256 (gw2)
#define NT     512
typedef unsigned int u32;
typedef unsigned short u16;

// ---------------- scratch (static device globals) ----------------------------
__device__ int   g_count[NE];
__device__ int   g_list[NE][BPTS];
__device__ float g_gv[BPTS];
// expert weights row-major [e][k][n(256)] fp16 hi / lo
__device__ u16 g_wh[NE * WROWS * 256];
__device__ u16 g_wl[NE * WROWS * 256];
// gate weights [k(576)][n(256)] fp16 hi / lo
__device__ u16 g_gh[GWROWS * 256];
__device__ u16 g_gl[GWROWS * 256];

// ---------------- tensor-core helpers ----------------------------------------
__device__ __forceinline__ void mma_f16(float d[4], u32 a0, u32 a1, u32 a2, u32 a3,
                                        u32 b0, u32 b1) {
    asm volatile(
        "mma.sync.aligned.m16n8k16.row.col.f32.f16.f16.f32 "
        "{%0,%1,%2,%3}, {%4,%5,%6,%7}, {%8,%9}, {%0,%1,%2,%3};"
        : "+f"(d[0]), "+f"(d[1]), "+f"(d[2]), "+f"(d[3])
        : "r"(a0), "r"(a1), "r"(a2), "r"(a3), "r"(b0), "r"(b1));
}
__device__ __forceinline__ void ldsm4(u32 r[4], u32 addr) {
    asm volatile("ldmatrix.sync.aligned.m8n8.x4.shared.b16 {%0,%1,%2,%3}, [%4];"
                 : "=r"(r[0]), "=r"(r[1]), "=r"(r[2]), "=r"(r[3]) : "r"(addr));
}
__device__ __forceinline__ void ldsm4t(u32 r[4], u32 addr) {
    asm volatile("ldmatrix.sync.aligned.m8n8.x4.trans.shared.b16 {%0,%1,%2,%3}, [%4];"
                 : "=r"(r[0]), "=r"(r[1]), "=r"(r[2]), "=r"(r[3]) : "r"(addr));
}
#define CP16(dst, src) \
    asm volatile("cp.async.cg.shared.global [%0], [%1], 16;" :: "r"(dst), "l"(src))
#define CPCOMMIT() asm volatile("cp.async.commit_group;")
#define CPWAIT0()  asm volatile("cp.async.wait_group 0;")

__device__ __forceinline__ void split2h(float v, u16& h, u16& l) {
    __half hh = __float2half_rn(v);
    __half ll = __float2half_rn(v - __half2float(hh));
    h = *(u16*)&hh;  l = *(u16*)&ll;
}

// ---------------- weight chunk staging (32 k-rows, hi+lo) ---------------------
// smem plane rows stride 264 u16 (528 B); lo plane at +16896 B. Buffer 33792 B.
__device__ __forceinline__ void stage_chunk32(
    u32 dst_base, const u16* __restrict__ Wh, const u16* __restrict__ Wl,
    int c, int tid) {
#pragma unroll
    for (int p = 0; p < 4; p++) {
        int uu = tid + p * NT;
        int isLo = uu >> 10;
        int v = uu & 1023;
        int row = v >> 5, col = v & 31;
        const u16* src = (isLo ? Wl : Wh) + (size_t)(c * 32 + row) * 256 + col * 8;
        u32 dst = dst_base + isLo * 16896 + row * 528 + col * 16;
        CP16(dst, src);
    }
}

// GEMM: acc[64x256] += A[64xK] @ W[Kx256]; A pre-split fp16 hi/lo planes in
// smem (ldmatrix), W staged hi/lo via cp.async double-buffered 32-row chunks.
// 16 warps: warp grid 2(M=32) x 8(N=32); acc[2][4][4] per thread.
__device__ __forceinline__ void gemm_tc3(
    float (&acc)[2][4][4],
    u32 a_hi_b, u32 a_lo_b, int rowbytes,
    const u16* __restrict__ Wh, const u16* __restrict__ Wl,
    int nc, u32 wstu, u32 bboff, int tid)
{
    stage_chunk32(wstu, Wh, Wl, 0, tid);
    CPCOMMIT();
    u32 ah[2][4], al[2][4], bh[4], bl[4];
    for (int c = 0; c < nc; c++) {
        CPWAIT0();
        __syncthreads();
        if (c + 1 < nc) {
            stage_chunk32(wstu + ((c + 1) & 1) * 33792, Wh, Wl, c + 1, tid);
            CPCOMMIT();
        }
        const u32 cur = wstu + (c & 1) * 33792;
#pragma unroll
        for (int ks = 0; ks < 2; ks++) {
            const u32 aoff = (u32)(c * 64 + ks * 32);
            ldsm4(ah[0], a_hi_b + aoff);
            ldsm4(ah[1], a_hi_b + 16 * rowbytes + aoff);
            ldsm4(al[0], a_lo_b + aoff);
            ldsm4(al[1], a_lo_b + 16 * rowbytes + aoff);
            const u32 bb = cur + bboff + ks * 8448;
#pragma unroll
            for (int gg = 0; gg < 2; gg++) {
                ldsm4t(bh, bb + gg * 32);
                ldsm4t(bl, bb + 16896 + gg * 32);
#pragma unroll
                for (int nb = 0; nb < 2; nb++) {
                    const int j = gg * 2 + nb;
                    const u32 b0 = bh[2 * nb], b1 = bh[2 * nb + 1];
                    const u32 c0 = bl[2 * nb], c1 = bl[2 * nb + 1];
#pragma unroll
                    for (int im = 0; im < 2; im++) {
                        mma_f16(acc[im][j], ah[im][0], ah[im][1], ah[im][2], ah[im][3], b0, b1);
                        mma_f16(acc[im][j], al[im][0], al[im][1], al[im][2], al[im][3], b0, b1);
                        mma_f16(acc[im][j], ah[im][0], ah[im][1], ah[im][2], ah[im][3], c0, c1);
                    }
                }
            }
        }
    }
}

__device__ __forceinline__ void zero_acc_tc(float (&acc)[2][4][4]) {
#pragma unroll
    for (int im = 0; im < 2; im++)
#pragma unroll
        for (int j = 0; j < 4; j++)
#pragma unroll
            for (int q = 0; q < 4; q++) acc[im][j][q] = 0.f;
}

// epilogue: relu(acc+bias) -> split fp16 hi/lo planes (stride 264)
__device__ __forceinline__ void epi_relu(const float (&acc)[2][4][4],
                                         const float* __restrict__ bias,
                                         u16* a_hi, u16* a_lo, int tid) {
    const int lane = tid & 31, wid = tid >> 5;
    const int m0 = (wid & 1) * 32, n_off = (wid >> 1) * 32;
    const int g = lane >> 2, tt = lane & 3;
#pragma unroll
    for (int im = 0; im < 2; im++)
#pragma unroll
        for (int j = 0; j < 4; j++) {
            const int c = n_off + j * 8 + 2 * tt;
            const float b0 = bias[c], b1 = bias[c + 1];
            const int rlo = m0 + im * 16 + g, rhi = rlo + 8;
            float v0 = fmaxf(acc[im][j][0] + b0, 0.f);
            float v1 = fmaxf(acc[im][j][1] + b1, 0.f);
            float v2 = fmaxf(acc[im][j][2] + b0, 0.f);
            float v3 = fmaxf(acc[im][j][3] + b1, 0.f);
            __half2 h01 = __floats2half2_rn(v0, v1);
            __half2 h23 = __floats2half2_rn(v2, v3);
            float2 hf01 = __half22float2(h01);
            float2 hf23 = __half22float2(h23);
            __half2 l01 = __floats2half2_rn(v0 - hf01.x, v1 - hf01.y);
            __half2 l23 = __floats2half2_rn(v2 - hf23.x, v3 - hf23.y);
            *(u32*)(a_hi + rlo * 264 + c) = *(u32*)&h01;
            *(u32*)(a_hi + rhi * 264 + c) = *(u32*)&h23;
            *(u32*)(a_lo + rlo * 264 + c) = *(u32*)&l01;
            *(u32*)(a_lo + rhi * 264 + c) = *(u32*)&l23;
        }
}

// gate GEMM2 epilogue: h2 = acc + bias (fp32, stride 257, no relu)
__device__ __forceinline__ void epi_h2(const float (&acc)[2][4][4],
                                       const float* __restrict__ bias,
                                       float* h2, int tid) {
    const int lane = tid & 31, wid = tid >> 5;
    const int m0 = (wid & 1) * 32, n_off = (wid >> 1) * 32;
    const int g = lane >> 2, tt = lane & 3;
#pragma unroll
    for (int im = 0; im < 2; im++)
#pragma unroll
        for (int j = 0; j < 4; j++) {
            const int c = n_off + j * 8 + 2 * tt;
            const float b0 = bias[c], b1 = bias[c + 1];
            const int rlo = m0 + im * 16 + g, rhi = rlo + 8;
            h2[rlo * 257 + c]     = acc[im][j][0] + b0;
            h2[rlo * 257 + c + 1] = acc[im][j][1] + b1;
            h2[rhi * 257 + c]     = acc[im][j][2] + b0;
            h2[rhi * 257 + c + 1] = acc[im][j][3] + b1;
        }
}

// ---------------- kernel 0: reset ---------------------------------------------
__global__ void reset_kernel() {
    if (threadIdx.x < NE) g_count[threadIdx.x] = 0;
}

// ---------------- kernel 0b: split expert weights to fp16 hi/lo ----------------
__global__ void convert_weights(
    const float* __restrict__ ew0, const float* __restrict__ ew1,
    const float* __restrict__ ew2, const float* __restrict__ ew3,
    const float* __restrict__ ew4, const float* __restrict__ ew5,
    const float* __restrict__ ew6) {
    int idx = blockIdx.x * 256 + threadIdx.x;          // < NE*WROWS*256
    int e   = idx / (WROWS * 256);
    int rem = idx - e * (WROWS * 256);
    int r = rem >> 8, n = rem & 255;
    float w = 0.f;
    if (r < 96)        { int k = r;            if (k < 95) w = ew0[((size_t)e * 95 + k) * 256 + n]; }
    else if (r < 352)  { int k = r - 96;       w = ew1[((size_t)e * 256 + k) * 256 + n]; }
    else if (r < 608)  { int k = r - 352;      w = ew2[((size_t)e * 256 + k) * 256 + n]; }
    else if (r < 864)  { int k = r - 608;      w = ew3[((size_t)e * 256 + k) * 256 + n]; }
    else if (r < 1120) { int k = r - 864;      w = ew4[((size_t)e * 256 + k) * 256 + n]; }
    else if (r < 1376) { int k = r - 1120;     w = ew5[((size_t)e * 351 + k) * 256 + n]; }
    else if (r < 1472) { int k = 256 + (r - 1376); if (k < 351) w = ew5[((size_t)e * 351 + k) * 256 + n]; }
    else               { int k = r - 1472;     w = ew6[((size_t)e * 256 + k) * 256 + n]; }
    split2h(w, g_wh[idx], g_wl[idx]);
}

// ---------------- kernel 0c: split gate weights --------------------------------
__global__ void convert_gate_weights(const float* __restrict__ gw1,
                                     const float* __restrict__ gw2) {
    int idx = blockIdx.x * 256 + threadIdx.x;          // < GWROWS*256
    int r = idx >> 8, n = idx & 255;
    float w = 0.f;
    if (r < 320) { if (r < 319) w = gw1[(size_t)r * 256 + n]; }
    else         w = gw2[(size_t)(r - 320) * 256 + n];
    split2h(w, g_gh[idx], g_gl[idx]);
}

// ---------------- kernel 1: gate network + routing (TC fp16-split) -------------
// smem bytes: region0 [0, 84992): gi planes (2 x 64x328 u16) -> h1 planes
//             (2 x 64x264 u16) -> h2 fp32 (64x257) + logits (at 66048)
//             wst at 84992: 2 x 33792 B
#define GATE_SMEM_B (84992 + 67584)

__global__ __launch_bounds__(NT, 1) void gate_kernel(
    const float* __restrict__ x,  const float* __restrict__ sl,
    const float* __restrict__ gb1, const float* __restrict__ gb2,
    const float* __restrict__ lng, const float* __restrict__ lnb,
    const float* __restrict__ gw3, const float* __restrict__ gb3) {
    extern __shared__ u16 smu[];
    u16* gi_hi = smu;                       // 64*328
    u16* gi_lo = smu + 20992;
    u16* a_hi  = smu;                       // 64*264 (after GEMM1)
    u16* a_lo  = smu + 16896;
    float* h2    = (float*)smu;             // 64*257 (after GEMM2)
    float* lgbuf = (float*)((char*)smu + 66048);   // 64*8
    const u32 wstu = (u32)__cvta_generic_to_shared((char*)smu + 84992);

    const int tid = threadIdx.x;
    const int row0 = blockIdx.x * 64;
    const int lane = tid & 31, wid = tid >> 5;
    const int m0 = (wid & 1) * 32, n_off = (wid >> 1) * 32;
    const u32 bboff = (u32)(((lane & 15) * 264 + n_off + (lane >> 4) * 8) * 2);

    // gather g_in = concat(x, shape_latent) split into fp16 hi/lo (stride 328)
    for (int idx = tid; idx < 64 * 328; idx += NT) {
        int r = idx / 328, c = idx - r * 328;
        int gi = row0 + r;
        float v = 0.f;
        if (c < 63)       v = x[gi * 63 + c];
        else if (c < 319) v = sl[gi * 256 + (c - 63)];
        split2h(v, gi_hi[idx], gi_lo[idx]);
    }
    __syncthreads();

    const u32 gihi_b = (u32)__cvta_generic_to_shared(gi_hi)
                     + (u32)((m0 + (lane & 15)) * 656) + (u32)((lane >> 4) * 16);
    const u32 gilo_b = (u32)__cvta_generic_to_shared(gi_lo)
                     + (u32)((m0 + (lane & 15)) * 656) + (u32)((lane >> 4) * 16);
    const u32 ahi_b = (u32)__cvta_generic_to_shared(a_hi)
                    + (u32)((m0 + (lane & 15)) * 528) + (u32)((lane >> 4) * 16);
    const u32 alo_b = (u32)__cvta_generic_to_shared(a_lo)
                    + (u32)((m0 + (lane & 15)) * 528) + (u32)((lane >> 4) * 16);

    float acc[2][4][4];

    // GEMM1: g_in (K=320) @ gw1 -> relu -> h1 split planes  (10 x 32-row chunks)
    zero_acc_tc(acc);
    gemm_tc3(acc, gihi_b, gilo_b, 656, g_gh, g_gl, 10, wstu, bboff, tid);
    __syncthreads();
    epi_relu(acc, gb1, a_hi, a_lo, tid);
    __syncthreads();

    // GEMM2: h1 (K=256) @ gw2 -> h2 fp32  (8 x 32-row chunks)
    zero_acc_tc(acc);
    gemm_tc3(acc, ahi_b, alo_b, 528, g_gh + 320 * 256, g_gl + 320 * 256,
             8, wstu, bboff, tid);
    __syncthreads();
    epi_h2(acc, gb2, h2, tid);
    __syncthreads();

    // LayerNorm per row: 8 threads/row, two-pass
    {
        int r = tid >> 3, sub = tid & 7;
        float* h2r = h2 + r * 257;
        float s = 0.f;
#pragma unroll 8
        for (int k = 0; k < 32; k++) s += h2r[sub + 8 * k];
        s += __shfl_xor_sync(0xffffffffu, s, 1);
        s += __shfl_xor_sync(0xffffffffu, s, 2);
        s += __shfl_xor_sync(0xffffffffu, s, 4);
        float mu = s * (1.f / 256.f);
        float vv = 0.f;
#pragma unroll 8
        for (int k = 0; k < 32; k++) {
            float d = h2r[sub + 8 * k] - mu;
            vv += d * d;
        }
        vv += __shfl_xor_sync(0xffffffffu, vv, 1);
        vv += __shfl_xor_sync(0xffffffffu, vv, 2);
        vv += __shfl_xor_sync(0xffffffffu, vv, 4);
        float rstd = rsqrtf(vv * (1.f / 256.f) + 1e-5f);
#pragma unroll 8
        for (int k = 0; k < 32; k++) {
            int c = sub + 8 * k;
            float nv = (h2r[c] - mu) * rstd;
            h2r[c] = nv * lng[c] + lnb[c];
        }
    }
    __syncthreads();

    // logits = h2 @ gw3 + gb3 (fp32 scalar; one task per thread)
    {
        int r = tid >> 3, e = tid & 7;
        float d = gb3[e];
        const float* h2r = h2 + r * 257;
#pragma unroll 8
        for (int k = 0; k < 256; k++) d += h2r[k] * gw3[k * 8 + e];
        lgbuf[r * 8 + e] = d;
    }
    __syncthreads();

    // softmax / argmax / append to expert list
    if (tid < 64) {
        int gi = row0 + tid;
        const float* lg = lgbuf + tid * 8;
        float best = lg[0];
        int bi = 0;
#pragma unroll
        for (int e = 1; e < 8; e++) {
            float v = lg[e];
            if (v > best) { best = v; bi = e; }
        }
        float ssum = 0.f;
#pragma unroll
        for (int e = 0; e < 8; e++) ssum += expf(lg[e] - best);
        g_gv[gi] = 1.f / ssum;
        int pos = atomicAdd(&g_count[bi], 1);
        g_list[bi][pos] = gi;
    }
}

// ---------------- kernel 2: routed expert MLP (TC, cp.async staged) -----------
// smem elems (u16): a_hi[16896] a_lo[16896] h_hi[6656] h_lo[6656] wst[2x16896]
#define EXP_SMEM_B ((16896 * 2 + 6656 * 2 + 33792) * 2)
#define EXP_TILES  (BPTS / 64 + NE)

__global__ __launch_bounds__(NT, 1) void expert_kernel(
    const float* __restrict__ x,  const float* __restrict__ sl,
    const float* __restrict__ eb0, const float* __restrict__ eb1,
    const float* __restrict__ eb2, const float* __restrict__ eb3,
    const float* __restrict__ eb4, const float* __restrict__ eb5,
    const float* __restrict__ eb6,
    const float* __restrict__ ewo, const float* __restrict__ ebo,
    float* __restrict__ out) {
    int t = blockIdx.x;
    int e, base = 0, n = 0;
    for (e = 0; e < NE; e++) {
        n = g_count[e];
        int T = (n + 63) >> 6;
        if (t < base + T) break;
        base += T;
    }
    if (e == NE) return;
    const int start = (t - base) * 64;
    const int nrows = min(64, n - start);

    extern __shared__ u16 smu[];
    u16* a_hi = smu;                    // 64*264
    u16* a_lo = smu + 16896;
    u16* h_hi = smu + 2 * 16896;        // 64*104
    u16* h_lo = h_hi + 6656;
    u16* wst  = smu + 2 * 16896 + 2 * 6656;
    __shared__ int ridx[64];
    const int tid = threadIdx.x;
    const int lane = tid & 31, wid = tid >> 5;
    const int m0 = (wid & 1) * 32, n_off = (wid >> 1) * 32;

    if (tid < 64) ridx[tid] = (tid < nrows) ? g_list[e][start + tid] : -1;
    __syncthreads();

    // gather h0 = concat(x, latent chunk e) split into fp16 hi/lo planes
    for (int idx = tid; idx < 64 * 104; idx += NT) {
        int r = idx / 104, c = idx - r * 104;
        int gi = ridx[r];
        float v = 0.f;
        if (gi >= 0) {
            if (c < 63)      v = x[gi * 63 + c];
            else if (c < 95) v = sl[gi * 256 + e * CHUNKD + (c - 63)];
        }
        split2h(v, h_hi[idx], h_lo[idx]);
    }
    __syncthreads();

    const u32 a_hi_b = (u32)__cvta_generic_to_shared(a_hi)
                     + (u32)((m0 + (lane & 15)) * 528) + (u32)((lane >> 4) * 16);
    const u32 a_lo_b = (u32)__cvta_generic_to_shared(a_lo)
                     + (u32)((m0 + (lane & 15)) * 528) + (u32)((lane >> 4) * 16);
    const u32 h_hi_b = (u32)__cvta_generic_to_shared(h_hi)
                     + (u32)((m0 + (lane & 15)) * 208) + (u32)((lane >> 4) * 16);
    const u32 h_lo_b = (u32)__cvta_generic_to_shared(h_lo)
                     + (u32)((m0 + (lane & 15)) * 208) + (u32)((lane >> 4) * 16);
    const u32 wstu = (u32)__cvta_generic_to_shared(wst);
    const u32 bboff = (u32)(((lane & 15) * 264 + n_off + (lane >> 4) * 8) * 2);

    const u16* WH = g_wh + (size_t)e * WROWS * 256;
    const u16* WL = g_wl + (size_t)e * WROWS * 256;
    float acc[2][4][4];

    // L0: h0 (K=96) -> 256  (3 x 32-row chunks)
    zero_acc_tc(acc);
    gemm_tc3(acc, h_hi_b, h_lo_b, 208, WH, WL, 3, wstu, bboff, tid);
    __syncthreads();
    epi_relu(acc, eb0 + e * 256, a_hi, a_lo, tid);
    __syncthreads();

    // L1..L4: 256 -> 256  (8 x 32-row chunks each)
    const float* bl4[4] = { eb1, eb2, eb3, eb4 };
#pragma unroll 1
    for (int l = 0; l < 4; l++) {
        zero_acc_tc(acc);
        gemm_tc3(acc, a_hi_b, a_lo_b, 528,
                 WH + (size_t)(96 + l * 256) * 256, WL + (size_t)(96 + l * 256) * 256,
                 8, wstu, bboff, tid);
        __syncthreads();
        epi_relu(acc, bl4[l] + e * 256, a_hi, a_lo, tid);
        __syncthreads();
    }

    // L5 (skip): act part (K=256) + h0 part (K=96)
    zero_acc_tc(acc);
    gemm_tc3(acc, a_hi_b, a_lo_b, 528,
             WH + (size_t)1120 * 256, WL + (size_t)1120 * 256, 8, wstu, bboff, tid);
    gemm_tc3(acc, h_hi_b, h_lo_b, 208,
             WH + (size_t)1376 * 256, WL + (size_t)1376 * 256, 3, wstu, bboff, tid);
    __syncthreads();
    epi_relu(acc, eb5 + e * 256, a_hi, a_lo, tid);
    __syncthreads();

    // L6
    zero_acc_tc(acc);
    gemm_tc3(acc, a_hi_b, a_lo_b, 528,
             WH + (size_t)1472 * 256, WL + (size_t)1472 * 256, 8, wstu, bboff, tid);
    __syncthreads();
    epi_relu(acc, eb6 + e * 256, a_hi, a_lo, tid);
    __syncthreads();

    // output head: y = act @ ewo[e] + ebo[e]; combine with gate
    if (tid < 256) {
        int r = tid >> 2, o = tid & 3;
        if (r < nrows) {
            float d = ebo[e * 4 + o];
            const float* wo = ewo + (size_t)e * 1024 + o;
            const __half2* ah2 = (const __half2*)(a_hi + r * 264);
            const __half2* al2 = (const __half2*)(a_lo + r * 264);
#pragma unroll 8
            for (int k = 0; k < 128; k++) {
                float2 hv = __half22float2(ah2[k]);
                float2 lv = __half22float2(al2[k]);
                d += (hv.x + lv.x) * wo[(2 * k) * 4];
                d += (hv.y + lv.y) * wo[(2 * k + 1) * 4];
            }
            int gi = ridx[r];
            float comb = g_gv[gi] * expf(d);
            if (comb == 0.f) comb = EPSF;
            out[gi * 4 + o] = logf(comb);
        }
    }
}

// ---------------- launch -----------------------------------------------------
// convert_weights runs on a side stream concurrent with the gate (it writes
// only g_wh/g_wl, which only expert_kernel reads); fork/join via events.
// Stream + events are created on the FIRST call (the uncaptured correctness
// run), so graph capture sees only launches + event record/wait.
extern "C" void kernel_launch(void* const* d_in, const int* in_sizes, int n_in,
                              void* d_out, int out_size) {
    const float* x   = (const float*)d_in[0];
    const float* sl  = (const float*)d_in[1];
    const float* gw1 = (const float*)d_in[2];
    const float* gb1 = (const float*)d_in[3];
    const float* gw2 = (const float*)d_in[4];
    const float* gb2 = (const float*)d_in[5];
    const float* lng = (const float*)d_in[6];
    const float* lnb = (const float*)d_in[7];
    const float* gw3 = (const float*)d_in[8];
    const float* gb3 = (const float*)d_in[9];
    const float* ew0 = (const float*)d_in[10];
    const float* eb0 = (const float*)d_in[11];
    const float* ew1 = (const float*)d_in[12];
    const float* eb1 = (const float*)d_in[13];
    const float* ew2 = (const float*)d_in[14];
    const float* eb2 = (const float*)d_in[15];
    const float* ew3 = (const float*)d_in[16];
    const float* eb3 = (const float*)d_in[17];
    const float* ew4 = (const float*)d_in[18];
    const float* eb4 = (const float*)d_in[19];
    const float* ew5 = (const float*)d_in[20];
    const float* eb5 = (const float*)d_in[21];
    const float* ew6 = (const float*)d_in[22];
    const float* eb6 = (const float*)d_in[23];
    const float* ewo = (const float*)d_in[24];
    const float* ebo = (const float*)d_in[25];
    float* out = (float*)d_out;

    static cudaStream_t s2 = nullptr;
    static cudaEvent_t evFork = nullptr, evJoin = nullptr;
    if (s2 == nullptr) {
        cudaStreamCreateWithFlags(&s2, cudaStreamNonBlocking);
        cudaEventCreateWithFlags(&evFork, cudaEventDisableTiming);
        cudaEventCreateWithFlags(&evJoin, cudaEventDisableTiming);
        cudaFuncSetAttribute(gate_kernel,
                             cudaFuncAttributeMaxDynamicSharedMemorySize, GATE_SMEM_B);
        cudaFuncSetAttribute(expert_kernel,
                             cudaFuncAttributeMaxDynamicSharedMemorySize, EXP_SMEM_B);
    }

    // fork: expert-weight conversion runs concurrently with the gate path
    cudaEventRecord(evFork, 0);
    cudaStreamWaitEvent(s2, evFork, 0);
    convert_weights<<<NE * WROWS, 256, 0, s2>>>(ew0, ew1, ew2, ew3, ew4, ew5, ew6);
    cudaEventRecord(evJoin, s2);

    // main path: reset + gate weights + gate
    reset_kernel<<<1, 32>>>();
    convert_gate_weights<<<GWROWS, 256>>>(gw1, gw2);
    gate_kernel<<<BPTS / 64, NT, GATE_SMEM_B>>>(x, sl, gb1, gb2,
                                                lng, lnb, gw3, gb3);

    // join: expert needs g_wh/g_wl
    cudaStreamWaitEvent(0, evJoin, 0);
    expert_kernel<<<EXP_TILES, NT, EXP_SMEM_B>>>(
        x, sl, eb0, eb1, eb2, eb3, eb4, eb5, eb6, ewo, ebo, out);
}

// round 15
// speedup vs baseline: 1.0694x; 1.0171x over previous
#include <cuda_runtime.h>
#include <cuda_fp16.h>

#define BPTS   16384
#define NE     8
#define CHUNKD 32
#define EPSF   2.220446049250313e-16f
#define WROWS  1728           // padded expert K rows: 96+4*256+256+96+256
#define GWROWS 576            // gate: 320 (gw1 padded) + 256 (gw2)
#define NT     512
typedef unsigned int u32;
typedef unsigned short u16;

// ---------------- scratch (static device globals) ----------------------------
__device__ int   g_count[NE];
__device__ int   g_list[NE][BPTS];
__device__ float g_gv[BPTS];
// expert weights row-major [e][k][n(256)] fp16 hi / lo
__device__ u16 g_wh[NE * WROWS * 256];
__device__ u16 g_wl[NE * WROWS * 256];
// gate weights [k(576)][n(256)] fp16 hi / lo
__device__ u16 g_gh[GWROWS * 256];
__device__ u16 g_gl[GWROWS * 256];

// ---------------- tensor-core helpers ----------------------------------------
__device__ __forceinline__ void mma_f16(float d[4], u32 a0, u32 a1, u32 a2, u32 a3,
                                        u32 b0, u32 b1) {
    asm volatile(
        "mma.sync.aligned.m16n8k16.row.col.f32.f16.f16.f32 "
        "{%0,%1,%2,%3}, {%4,%5,%6,%7}, {%8,%9}, {%0,%1,%2,%3};"
        : "+f"(d[0]), "+f"(d[1]), "+f"(d[2]), "+f"(d[3])
        : "r"(a0), "r"(a1), "r"(a2), "r"(a3), "r"(b0), "r"(b1));
}
__device__ __forceinline__ void ldsm4(u32 r[4], u32 addr) {
    asm volatile("ldmatrix.sync.aligned.m8n8.x4.shared.b16 {%0,%1,%2,%3}, [%4];"
                 : "=r"(r[0]), "=r"(r[1]), "=r"(r[2]), "=r"(r[3]) : "r"(addr));
}
__device__ __forceinline__ void ldsm4t(u32 r[4], u32 addr) {
    asm volatile("ldmatrix.sync.aligned.m8n8.x4.trans.shared.b16 {%0,%1,%2,%3}, [%4];"
                 : "=r"(r[0]), "=r"(r[1]), "=r"(r[2]), "=r"(r[3]) : "r"(addr));
}
#define CP16(dst, src) \
    asm volatile("cp.async.cg.shared.global [%0], [%1], 16;" :: "r"(dst), "l"(src))
#define CPCOMMIT() asm volatile("cp.async.commit_group;")
#define CPWAIT0()  asm volatile("cp.async.wait_group 0;")
#define CPWAIT1()  asm volatile("cp.async.wait_group 1;")

__device__ __forceinline__ void split2h(float v, u16& h, u16& l) {
    __half hh = __float2half_rn(v);
    __half ll = __float2half_rn(v - __half2float(hh));
    h = *(u16*)&hh;  l = *(u16*)&ll;
}

// ---------------- per-warp weight slice staging -------------------------------
// Each warp stages its own 32-row x 16-col slice, hi+lo, into its private
// region: rows stride 48 B (conflict-free ldsm), plane lo at +1536 B.
// One buffer = 3072 B; 2 buffers per warp (6144 B). 4 CP16 per lane per chunk.
__device__ __forceinline__ void stage_ws(u32 dstb,
                                         const u16* __restrict__ Whs,
                                         const u16* __restrict__ Wls,
                                         int c, int lane) {
#pragma unroll
    for (int p = 0; p < 4; p++) {
        int idx = lane + p * 32;       // 0..127
        int pl  = idx >> 6;            // 0 = hi, 1 = lo
        int v   = idx & 63;
        int row = v >> 1, half = v & 1;
        const u16* src = (pl ? Wls : Whs) + (size_t)(c * 32 + row) * 256 + half * 8;
        u32 dst = dstb + (u32)(pl * 1536 + row * 48 + half * 16);
        CP16(dst, src);
    }
}

// Warp-decoupled GEMM: acc[64 x 16-slice] += A[64xK] @ W[Kx16-slice].
// A pre-split fp16 hi/lo planes in shared smem (read-only here); W staged into
// the warp's private ring via its own cp.async groups. NO __syncthreads.
// Warp grid 1(M=64) x 16(N=16); acc[4][2][4] per thread.
__device__ __forceinline__ void gemm_ws(
    float (&acc)[4][2][4],
    u32 a_hi_b, u32 a_lo_b, int rowbytes,
    const u16* __restrict__ Whs, const u16* __restrict__ Wls,
    int nc, u32 wbase, int lane)
{
    stage_ws(wbase, Whs, Wls, 0, lane);
    CPCOMMIT();
    u32 ah[4][4], al[4][4], bh[4], bl[4];
    for (int c = 0; c < nc; c++) {
        if (c + 1 < nc) {
            stage_ws(wbase + (u32)(((c + 1) & 1) * 3072), Whs, Wls, c + 1, lane);
            CPCOMMIT();
            CPWAIT1();
        } else {
            CPWAIT0();
        }
        __syncwarp();
        const u32 cur = wbase + (u32)((c & 1) * 3072);
#pragma unroll
        for (int ks = 0; ks < 2; ks++) {
            const u32 aoff = (u32)(c * 64 + ks * 32);
#pragma unroll
            for (int mt = 0; mt < 4; mt++) {
                ldsm4(ah[mt], a_hi_b + (u32)(mt * 16 * rowbytes) + aoff);
                ldsm4(al[mt], a_lo_b + (u32)(mt * 16 * rowbytes) + aoff);
            }
            const u32 baddr = cur + (u32)((ks * 16 + (lane & 15)) * 48
                                          + (lane >> 4) * 16);
            ldsm4t(bh, baddr);
            ldsm4t(bl, baddr + 1536);
#pragma unroll
            for (int mt = 0; mt < 4; mt++)
#pragma unroll
                for (int nb = 0; nb < 2; nb++) {
                    const u32 b0 = bh[2 * nb], b1 = bh[2 * nb + 1];
                    const u32 c0 = bl[2 * nb], c1 = bl[2 * nb + 1];
                    mma_f16(acc[mt][nb], ah[mt][0], ah[mt][1], ah[mt][2], ah[mt][3], b0, b1);
                    mma_f16(acc[mt][nb], al[mt][0], al[mt][1], al[mt][2], al[mt][3], b0, b1);
                    mma_f16(acc[mt][nb], ah[mt][0], ah[mt][1], ah[mt][2], ah[mt][3], c0, c1);
                }
        }
    }
}

__device__ __forceinline__ void zero_acc_tc(float (&acc)[4][2][4]) {
#pragma unroll
    for (int mt = 0; mt < 4; mt++)
#pragma unroll
        for (int nb = 0; nb < 2; nb++)
#pragma unroll
            for (int q = 0; q < 4; q++) acc[mt][nb][q] = 0.f;
}

// epilogue: relu(acc+bias) -> split fp16 hi/lo planes (stride 264)
__device__ __forceinline__ void epi_relu(const float (&acc)[4][2][4],
                                         const float* __restrict__ bias,
                                         u16* a_hi, u16* a_lo, int tid) {
    const int lane = tid & 31, wid = tid >> 5;
    const int n_off = wid * 16;
    const int g = lane >> 2, tt = lane & 3;
#pragma unroll
    for (int mt = 0; mt < 4; mt++)
#pragma unroll
        for (int nb = 0; nb < 2; nb++) {
            const int c = n_off + nb * 8 + 2 * tt;
            const float b0 = bias[c], b1 = bias[c + 1];
            const int rlo = mt * 16 + g, rhi = rlo + 8;
            float v0 = fmaxf(acc[mt][nb][0] + b0, 0.f);
            float v1 = fmaxf(acc[mt][nb][1] + b1, 0.f);
            float v2 = fmaxf(acc[mt][nb][2] + b0, 0.f);
            float v3 = fmaxf(acc[mt][nb][3] + b1, 0.f);
            __half2 h01 = __floats2half2_rn(v0, v1);
            __half2 h23 = __floats2half2_rn(v2, v3);
            float2 hf01 = __half22float2(h01);
            float2 hf23 = __half22float2(h23);
            __half2 l01 = __floats2half2_rn(v0 - hf01.x, v1 - hf01.y);
            __half2 l23 = __floats2half2_rn(v2 - hf23.x, v3 - hf23.y);
            *(u32*)(a_hi + rlo * 264 + c) = *(u32*)&h01;
            *(u32*)(a_hi + rhi * 264 + c) = *(u32*)&h23;
            *(u32*)(a_lo + rlo * 264 + c) = *(u32*)&l01;
            *(u32*)(a_lo + rhi * 264 + c) = *(u32*)&l23;
        }
}

// gate GEMM2 epilogue: h2 = acc + bias (fp32, stride 257, no relu)
__device__ __forceinline__ void epi_h2(const float (&acc)[4][2][4],
                                       const float* __restrict__ bias,
                                       float* h2, int tid) {
    const int lane = tid & 31, wid = tid >> 5;
    const int n_off = wid * 16;
    const int g = lane >> 2, tt = lane & 3;
#pragma unroll
    for (int mt = 0; mt < 4; mt++)
#pragma unroll
        for (int nb = 0; nb < 2; nb++) {
            const int c = n_off + nb * 8 + 2 * tt;
            const float b0 = bias[c], b1 = bias[c + 1];
            const int rlo = mt * 16 + g, rhi = rlo + 8;
            h2[rlo * 257 + c]     = acc[mt][nb][0] + b0;
            h2[rlo * 257 + c + 1] = acc[mt][nb][1] + b1;
            h2[rhi * 257 + c]     = acc[mt][nb][2] + b0;
            h2[rhi * 257 + c + 1] = acc[mt][nb][3] + b1;
        }
}

// ---------------- kernel 0: reset ---------------------------------------------
__global__ void reset_kernel() {
    if (threadIdx.x < NE) g_count[threadIdx.x] = 0;
}

// ---------------- kernel 0b: split expert weights to fp16 hi/lo ----------------
__global__ void convert_weights(
    const float* __restrict__ ew0, const float* __restrict__ ew1,
    const float* __restrict__ ew2, const float* __restrict__ ew3,
    const float* __restrict__ ew4, const float* __restrict__ ew5,
    const float* __restrict__ ew6) {
    int idx = blockIdx.x * 256 + threadIdx.x;          // < NE*WROWS*256
    int e   = idx / (WROWS * 256);
    int rem = idx - e * (WROWS * 256);
    int r = rem >> 8, n = rem & 255;
    float w = 0.f;
    if (r < 96)        { int k = r;            if (k < 95) w = ew0[((size_t)e * 95 + k) * 256 + n]; }
    else if (r < 352)  { int k = r - 96;       w = ew1[((size_t)e * 256 + k) * 256 + n]; }
    else if (r < 608)  { int k = r - 352;      w = ew2[((size_t)e * 256 + k) * 256 + n]; }
    else if (r < 864)  { int k = r - 608;      w = ew3[((size_t)e * 256 + k) * 256 + n]; }
    else if (r < 1120) { int k = r - 864;      w = ew4[((size_t)e * 256 + k) * 256 + n]; }
    else if (r < 1376) { int k = r - 1120;     w = ew5[((size_t)e * 351 + k) * 256 + n]; }
    else if (r < 1472) { int k = 256 + (r - 1376); if (k < 351) w = ew5[((size_t)e * 351 + k) * 256 + n]; }
    else               { int k = r - 1472;     w = ew6[((size_t)e * 256 + k) * 256 + n]; }
    split2h(w, g_wh[idx], g_wl[idx]);
}

// ---------------- kernel 0c: split gate weights --------------------------------
__global__ void convert_gate_weights(const float* __restrict__ gw1,
                                     const float* __restrict__ gw2) {
    int idx = blockIdx.x * 256 + threadIdx.x;          // < GWROWS*256
    int r = idx >> 8, n = idx & 255;
    float w = 0.f;
    if (r < 320) { if (r < 319) w = gw1[(size_t)r * 256 + n]; }
    else         w = gw2[(size_t)(r - 320) * 256 + n];
    split2h(w, g_gh[idx], g_gl[idx]);
}

// ---------------- kernel 1: gate network + routing (TC fp16-split) -------------
// smem bytes: region0 [0, 84992): gi planes (2 x 64x328 u16) -> h1 planes
//             (2 x 64x264 u16) -> h2 fp32 (64x257) + logits (at 66048)
//             per-warp wst at 84992: 16 x 6144 B
#define GATE_SMEM_B (84992 + 98304)

__global__ __launch_bounds__(NT, 1) void gate_kernel(
    const float* __restrict__ x,  const float* __restrict__ sl,
    const float* __restrict__ gb1, const float* __restrict__ gb2,
    const float* __restrict__ lng, const float* __restrict__ lnb,
    const float* __restrict__ gw3, const float* __restrict__ gb3) {
    extern __shared__ u16 smu[];
    u16* gi_hi = smu;                       // 64*328
    u16* gi_lo = smu + 20992;
    u16* a_hi  = smu;                       // 64*264 (after GEMM1)
    u16* a_lo  = smu + 16896;
    float* h2    = (float*)smu;             // 64*257 (after GEMM2)
    float* lgbuf = (float*)((char*)smu + 66048);   // 64*8
    const u32 wstu = (u32)__cvta_generic_to_shared((char*)smu + 84992);

    const int tid = threadIdx.x;
    const int row0 = blockIdx.x * 64;
    const int lane = tid & 31, wid = tid >> 5;
    const u32 wbase = wstu + (u32)(wid * 6144);

    // gather g_in = concat(x, shape_latent) split into fp16 hi/lo (stride 328)
    for (int idx = tid; idx < 64 * 328; idx += NT) {
        int r = idx / 328, c = idx - r * 328;
        int gi = row0 + r;
        float v = 0.f;
        if (c < 63)       v = x[gi * 63 + c];
        else if (c < 319) v = sl[gi * 256 + (c - 63)];
        split2h(v, gi_hi[idx], gi_lo[idx]);
    }
    __syncthreads();

    const u32 gihi_b = (u32)__cvta_generic_to_shared(gi_hi)
                     + (u32)((lane & 15) * 656) + (u32)((lane >> 4) * 16);
    const u32 gilo_b = (u32)__cvta_generic_to_shared(gi_lo)
                     + (u32)((lane & 15) * 656) + (u32)((lane >> 4) * 16);
    const u32 ahi_b = (u32)__cvta_generic_to_shared(a_hi)
                    + (u32)((lane & 15) * 528) + (u32)((lane >> 4) * 16);
    const u32 alo_b = (u32)__cvta_generic_to_shared(a_lo)
                    + (u32)((lane & 15) * 528) + (u32)((lane >> 4) * 16);

    float acc[4][2][4];

    // GEMM1: g_in (K=320) @ gw1 -> relu -> h1 split planes  (10 chunks, no bar)
    zero_acc_tc(acc);
    gemm_ws(acc, gihi_b, gilo_b, 656, g_gh + wid * 16, g_gl + wid * 16,
            10, wbase, lane);
    __syncthreads();
    epi_relu(acc, gb1, a_hi, a_lo, tid);
    __syncthreads();

    // GEMM2: h1 (K=256) @ gw2 -> h2 fp32  (8 chunks, no bar)
    zero_acc_tc(acc);
    gemm_ws(acc, ahi_b, alo_b, 528, g_gh + 320 * 256 + wid * 16,
            g_gl + 320 * 256 + wid * 16, 8, wbase, lane);
    __syncthreads();
    epi_h2(acc, gb2, h2, tid);
    __syncthreads();

    // LayerNorm per row: 8 threads/row, two-pass
    {
        int r = tid >> 3, sub = tid & 7;
        float* h2r = h2 + r * 257;
        float s = 0.f;
#pragma unroll 8
        for (int k = 0; k < 32; k++) s += h2r[sub + 8 * k];
        s += __shfl_xor_sync(0xffffffffu, s, 1);
        s += __shfl_xor_sync(0xffffffffu, s, 2);
        s += __shfl_xor_sync(0xffffffffu, s, 4);
        float mu = s * (1.f / 256.f);
        float vv = 0.f;
#pragma unroll 8
        for (int k = 0; k < 32; k++) {
            float d = h2r[sub + 8 * k] - mu;
            vv += d * d;
        }
        vv += __shfl_xor_sync(0xffffffffu, vv, 1);
        vv += __shfl_xor_sync(0xffffffffu, vv, 2);
        vv += __shfl_xor_sync(0xffffffffu, vv, 4);
        float rstd = rsqrtf(vv * (1.f / 256.f) + 1e-5f);
#pragma unroll 8
        for (int k = 0; k < 32; k++) {
            int c = sub + 8 * k;
            float nv = (h2r[c] - mu) * rstd;
            h2r[c] = nv * lng[c] + lnb[c];
        }
    }
    __syncthreads();

    // logits = h2 @ gw3 + gb3 (fp32 scalar; one task per thread)
    {
        int r = tid >> 3, e = tid & 7;
        float d = gb3[e];
        const float* h2r = h2 + r * 257;
#pragma unroll 8
        for (int k = 0; k < 256; k++) d += h2r[k] * gw3[k * 8 + e];
        lgbuf[r * 8 + e] = d;
    }
    __syncthreads();

    // softmax / argmax / append to expert list
    if (tid < 64) {
        int gi = row0 + tid;
        const float* lg = lgbuf + tid * 8;
        float best = lg[0];
        int bi = 0;
#pragma unroll
        for (int e = 1; e < 8; e++) {
            float v = lg[e];
            if (v > best) { best = v; bi = e; }
        }
        float ssum = 0.f;
#pragma unroll
        for (int e = 0; e < 8; e++) ssum += expf(lg[e] - best);
        g_gv[gi] = 1.f / ssum;
        int pos = atomicAdd(&g_count[bi], 1);
        g_list[bi][pos] = gi;
    }
}

// ---------------- kernel 2: routed expert MLP (TC, warp-decoupled) ------------
// smem: a planes 2x33792B? (u16 counts) a_hi[16896] a_lo[16896] h_hi[6656]
//       h_lo[6656] | per-warp wst 16 x 6144 B
#define EXP_SMEM_B ((16896 * 2 + 6656 * 2) * 2 + 98304)
#define EXP_TILES  (BPTS / 64 + NE)

__global__ __launch_bounds__(NT, 1) void expert_kernel(
    const float* __restrict__ x,  const float* __restrict__ sl,
    const float* __restrict__ eb0, const float* __restrict__ eb1,
    const float* __restrict__ eb2, const float* __restrict__ eb3,
    const float* __restrict__ eb4, const float* __restrict__ eb5,
    const float* __restrict__ eb6,
    const float* __restrict__ ewo, const float* __restrict__ ebo,
    float* __restrict__ out) {
    int t = blockIdx.x;
    int e, base = 0, n = 0;
    for (e = 0; e < NE; e++) {
        n = g_count[e];
        int T = (n + 63) >> 6;
        if (t < base + T) break;
        base += T;
    }
    if (e == NE) return;
    const int start = (t - base) * 64;
    const int nrows = min(64, n - start);

    extern __shared__ u16 smu[];
    u16* a_hi = smu;                    // 64*264
    u16* a_lo = smu + 16896;
    u16* h_hi = smu + 2 * 16896;        // 64*104
    u16* h_lo = h_hi + 6656;
    const u32 wstu = (u32)__cvta_generic_to_shared(smu + 2 * 16896 + 2 * 6656);
    __shared__ int ridx[64];
    const int tid = threadIdx.x;
    const int lane = tid & 31, wid = tid >> 5;
    const u32 wbase = wstu + (u32)(wid * 6144);

    if (tid < 64) ridx[tid] = (tid < nrows) ? g_list[e][start + tid] : -1;
    __syncthreads();

    // gather h0 = concat(x, latent chunk e) split into fp16 hi/lo planes
    for (int idx = tid; idx < 64 * 104; idx += NT) {
        int r = idx / 104, c = idx - r * 104;
        int gi = ridx[r];
        float v = 0.f;
        if (gi >= 0) {
            if (c < 63)      v = x[gi * 63 + c];
            else if (c < 95) v = sl[gi * 256 + e * CHUNKD + (c - 63)];
        }
        split2h(v, h_hi[idx], h_lo[idx]);
    }
    __syncthreads();

    const u32 a_hi_b = (u32)__cvta_generic_to_shared(a_hi)
                     + (u32)((lane & 15) * 528) + (u32)((lane >> 4) * 16);
    const u32 a_lo_b = (u32)__cvta_generic_to_shared(a_lo)
                     + (u32)((lane & 15) * 528) + (u32)((lane >> 4) * 16);
    const u32 h_hi_b = (u32)__cvta_generic_to_shared(h_hi)
                     + (u32)((lane & 15) * 208) + (u32)((lane >> 4) * 16);
    const u32 h_lo_b = (u32)__cvta_generic_to_shared(h_lo)
                     + (u32)((lane & 15) * 208) + (u32)((lane >> 4) * 16);

    const u16* WH = g_wh + (size_t)e * WROWS * 256 + wid * 16;
    const u16* WL = g_wl + (size_t)e * WROWS * 256 + wid * 16;
    float acc[4][2][4];

    // L0: h0 (K=96) -> 256  (3 chunks, no bar)
    zero_acc_tc(acc);
    gemm_ws(acc, h_hi_b, h_lo_b, 208, WH, WL, 3, wbase, lane);
    __syncthreads();
    epi_relu(acc, eb0 + e * 256, a_hi, a_lo, tid);
    __syncthreads();

    // L1..L4: 256 -> 256  (8 chunks each, no bar)
    const float* bl4[4] = { eb1, eb2, eb3, eb4 };
#pragma unroll 1
    for (int l = 0; l < 4; l++) {
        zero_acc_tc(acc);
        gemm_ws(acc, a_hi_b, a_lo_b, 528,
                WH + (size_t)(96 + l * 256) * 256, WL + (size_t)(96 + l * 256) * 256,
                8, wbase, lane);
        __syncthreads();
        epi_relu(acc, bl4[l] + e * 256, a_hi, a_lo, tid);
        __syncthreads();
    }

    // L5 (skip): act part (K=256) + h0 part (K=96); both per-warp, no bar
    zero_acc_tc(acc);
    gemm_ws(acc, a_hi_b, a_lo_b, 528,
            WH + (size_t)1120 * 256, WL + (size_t)1120 * 256, 8, wbase, lane);
    gemm_ws(acc, h_hi_b, h_lo_b, 208,
            WH + (size_t)1376 * 256, WL + (size_t)1376 * 256, 3, wbase, lane);
    __syncthreads();
    epi_relu(acc, eb5 + e * 256, a_hi, a_lo, tid);
    __syncthreads();

    // L6
    zero_acc_tc(acc);
    gemm_ws(acc, a_hi_b, a_lo_b, 528,
            WH + (size_t)1472 * 256, WL + (size_t)1472 * 256, 8, wbase, lane);
    __syncthreads();
    epi_relu(acc, eb6 + e * 256, a_hi, a_lo, tid);
    __syncthreads();

    // output head: y = act @ ewo[e] + ebo[e]; combine with gate
    if (tid < 256) {
        int r = tid >> 2, o = tid & 3;
        if (r < nrows) {
            float d = ebo[e * 4 + o];
            const float* wo = ewo + (size_t)e * 1024 + o;
            const __half2* ah2 = (const __half2*)(a_hi + r * 264);
            const __half2* al2 = (const __half2*)(a_lo + r * 264);
#pragma unroll 8
            for (int k = 0; k < 128; k++) {
                float2 hv = __half22float2(ah2[k]);
                float2 lv = __half22float2(al2[k]);
                d += (hv.x + lv.x) * wo[(2 * k) * 4];
                d += (hv.y + lv.y) * wo[(2 * k + 1) * 4];
            }
            int gi = ridx[r];
            float comb = g_gv[gi] * expf(d);
            if (comb == 0.f) comb = EPSF;
            out[gi * 4 + o] = logf(comb);
        }
    }
}

// ---------------- launch -----------------------------------------------------
extern "C" void kernel_launch(void* const* d_in, const int* in_sizes, int n_in,
                              void* d_out, int out_size) {
    const float* x   = (const float*)d_in[0];
    const float* sl  = (const float*)d_in[1];
    const float* gw1 = (const float*)d_in[2];
    const float* gb1 = (const float*)d_in[3];
    const float* gw2 = (const float*)d_in[4];
    const float* gb2 = (const float*)d_in[5];
    const float* lng = (const float*)d_in[6];
    const float* lnb = (const float*)d_in[7];
    const float* gw3 = (const float*)d_in[8];
    const float* gb3 = (const float*)d_in[9];
    const float* ew0 = (const float*)d_in[10];
    const float* eb0 = (const float*)d_in[11];
    const float* ew1 = (const float*)d_in[12];
    const float* eb1 = (const float*)d_in[13];
    const float* ew2 = (const float*)d_in[14];
    const float* eb2 = (const float*)d_in[15];
    const float* ew3 = (const float*)d_in[16];
    const float* eb3 = (const float*)d_in[17];
    const float* ew4 = (const float*)d_in[18];
    const float* eb4 = (const float*)d_in[19];
    const float* ew5 = (const float*)d_in[20];
    const float* eb5 = (const float*)d_in[21];
    const float* ew6 = (const float*)d_in[22];
    const float* eb6 = (const float*)d_in[23];
    const float* ewo = (const float*)d_in[24];
    const float* ebo = (const float*)d_in[25];
    float* out = (float*)d_out;

    static cudaStream_t s2 = nullptr;
    static cudaEvent_t evFork = nullptr, evJoin = nullptr;
    if (s2 == nullptr) {
        cudaStreamCreateWithFlags(&s2, cudaStreamNonBlocking);
        cudaEventCreateWithFlags(&evFork, cudaEventDisableTiming);
        cudaEventCreateWithFlags(&evJoin, cudaEventDisableTiming);
        cudaFuncSetAttribute(gate_kernel,
                             cudaFuncAttributeMaxDynamicSharedMemorySize, GATE_SMEM_B);
        cudaFuncSetAttribute(expert_kernel,
                             cudaFuncAttributeMaxDynamicSharedMemorySize, EXP_SMEM_B);
    }

    // fork: expert-weight conversion runs concurrently with the gate path
    cudaEventRecord(evFork, 0);
    cudaStreamWaitEvent(s2, evFork, 0);
    convert_weights<<<NE * WROWS, 256, 0, s2>>>(ew0, ew1, ew2, ew3, ew4, ew5, ew6);
    cudaEventRecord(evJoin, s2);

    // main path: reset + gate weights + gate
    reset_kernel<<<1, 32>>>();
    convert_gate_weights<<<GWROWS, 256>>>(gw1, gw2);
    gate_kernel<<<BPTS / 64, NT, GATE_SMEM_B>>>(x, sl, gb1, gb2,
                                                lng, lnb, gw3, gb3);

    // join: expert needs g_wh/g_wl
    cudaStreamWaitEvent(0, evJoin, 0);
    expert_kernel<<<EXP_TILES, NT, EXP_SMEM_B>>>(
        x, sl, eb0, eb1, eb2, eb3, eb4, eb5, eb6, ewo, ebo, out);
}

// round 16
// speedup vs baseline: 1.1772x; 1.1008x over previous
#include <cuda_runtime.h>
#include <cuda_fp16.h>

#define BPTS   16384
#define NE     8
#define CHUNKD 32
#define EPSF   2.220446049250313e-16f
#define WROWS  1728           // padded expert K rows: 96+4*256+256+96+256
#define GWROWS 576            // gate: 320 (gw1 padded) + 256 (gw2)
#define NT     512
typedef unsigned int u32;
typedef unsigned short u16;

// ---------------- scratch (static device globals) ----------------------------
__device__ int   g_count[NE];
__device__ int   g_list[NE][BPTS];
__device__ float g_gv[BPTS];
// expert weights row-major [e][k][n(256)] fp16 hi / lo
__device__ u16 g_wh[NE * WROWS * 256];
__device__ u16 g_wl[NE * WROWS * 256];
// gate weights [k(576)][n(256)] fp16 hi / lo
__device__ u16 g_gh[GWROWS * 256];
__device__ u16 g_gl[GWROWS * 256];

// ---------------- tensor-core helpers ----------------------------------------
__device__ __forceinline__ void mma_f16(float d[4], u32 a0, u32 a1, u32 a2, u32 a3,
                                        u32 b0, u32 b1) {
    asm volatile(
        "mma.sync.aligned.m16n8k16.row.col.f32.f16.f16.f32 "
        "{%0,%1,%2,%3}, {%4,%5,%6,%7}, {%8,%9}, {%0,%1,%2,%3};"
        : "+f"(d[0]), "+f"(d[1]), "+f"(d[2]), "+f"(d[3])
        : "r"(a0), "r"(a1), "r"(a2), "r"(a3), "r"(b0), "r"(b1));
}
__device__ __forceinline__ void ldsm4(u32 r[4], u32 addr) {
    asm volatile("ldmatrix.sync.aligned.m8n8.x4.shared.b16 {%0,%1,%2,%3}, [%4];"
                 : "=r"(r[0]), "=r"(r[1]), "=r"(r[2]), "=r"(r[3]) : "r"(addr));
}
__device__ __forceinline__ void ldsm4t(u32 r[4], u32 addr) {
    asm volatile("ldmatrix.sync.aligned.m8n8.x4.trans.shared.b16 {%0,%1,%2,%3}, [%4];"
                 : "=r"(r[0]), "=r"(r[1]), "=r"(r[2]), "=r"(r[3]) : "r"(addr));
}
#define CP16(dst, src) \
    asm volatile("cp.async.cg.shared.global [%0], [%1], 16;" :: "r"(dst), "l"(src))
#define CPCOMMIT() asm volatile("cp.async.commit_group;")
#define CPWAIT0()  asm volatile("cp.async.wait_group 0;")
#define CPWAIT1()  asm volatile("cp.async.wait_group 1;")

__device__ __forceinline__ void split2h(float v, u16& h, u16& l) {
    __half hh = __float2half_rn(v);
    __half ll = __float2half_rn(v - __half2float(hh));
    h = *(u16*)&hh;  l = *(u16*)&ll;
}

// ---------------- per-warp weight slice staging -------------------------------
// hi+lo variant (gate): buffer 3072 B (lo at +1536), ring 6144 B/warp.
__device__ __forceinline__ void stage_ws(u32 dstb,
                                         const u16* __restrict__ Whs,
                                         const u16* __restrict__ Wls,
                                         int c, int lane) {
#pragma unroll
    for (int p = 0; p < 4; p++) {
        int idx = lane + p * 32;       // 0..127
        int pl  = idx >> 6;            // 0 = hi, 1 = lo
        int v   = idx & 63;
        int row = v >> 1, half = v & 1;
        const u16* src = (pl ? Wls : Whs) + (size_t)(c * 32 + row) * 256 + half * 8;
        u32 dst = dstb + (u32)(pl * 1536 + row * 48 + half * 16);
        CP16(dst, src);
    }
}
// hi-only variant (expert, 2-term): buffer 1536 B, ring 3072 B/warp.
__device__ __forceinline__ void stage_ws_hi(u32 dstb,
                                            const u16* __restrict__ Whs,
                                            int c, int lane) {
#pragma unroll
    for (int p = 0; p < 2; p++) {
        int idx = lane + p * 32;       // 0..63
        int row = idx >> 1, half = idx & 1;
        const u16* src = Whs + (size_t)(c * 32 + row) * 256 + half * 8;
        u32 dst = dstb + (u32)(row * 48 + half * 16);
        CP16(dst, src);
    }
}

// Warp-decoupled 3-term GEMM (gate): acc[64 x 16] += A @ W, W hi+lo.
__device__ __forceinline__ void gemm_ws(
    float (&acc)[4][2][4],
    u32 a_hi_b, u32 a_lo_b, int rowbytes,
    const u16* __restrict__ Whs, const u16* __restrict__ Wls,
    int nc, u32 wbase, int lane)
{
    stage_ws(wbase, Whs, Wls, 0, lane);
    CPCOMMIT();
    u32 ah[4][4], al[4][4], bh[4], bl[4];
    for (int c = 0; c < nc; c++) {
        if (c + 1 < nc) {
            stage_ws(wbase + (u32)(((c + 1) & 1) * 3072), Whs, Wls, c + 1, lane);
            CPCOMMIT();
            CPWAIT1();
        } else {
            CPWAIT0();
        }
        __syncwarp();
        const u32 cur = wbase + (u32)((c & 1) * 3072);
#pragma unroll
        for (int ks = 0; ks < 2; ks++) {
            const u32 aoff = (u32)(c * 64 + ks * 32);
#pragma unroll
            for (int mt = 0; mt < 4; mt++) {
                ldsm4(ah[mt], a_hi_b + (u32)(mt * 16 * rowbytes) + aoff);
                ldsm4(al[mt], a_lo_b + (u32)(mt * 16 * rowbytes) + aoff);
            }
            const u32 baddr = cur + (u32)((ks * 16 + (lane & 15)) * 48
                                          + (lane >> 4) * 16);
            ldsm4t(bh, baddr);
            ldsm4t(bl, baddr + 1536);
#pragma unroll
            for (int mt = 0; mt < 4; mt++)
#pragma unroll
                for (int nb = 0; nb < 2; nb++) {
                    const u32 b0 = bh[2 * nb], b1 = bh[2 * nb + 1];
                    const u32 c0 = bl[2 * nb], c1 = bl[2 * nb + 1];
                    mma_f16(acc[mt][nb], ah[mt][0], ah[mt][1], ah[mt][2], ah[mt][3], b0, b1);
                    mma_f16(acc[mt][nb], al[mt][0], al[mt][1], al[mt][2], al[mt][3], b0, b1);
                    mma_f16(acc[mt][nb], ah[mt][0], ah[mt][1], ah[mt][2], ah[mt][3], c0, c1);
                }
        }
    }
}

// Warp-decoupled 2-term GEMM (expert): weights fp16 hi only.
__device__ __forceinline__ void gemm_ws2(
    float (&acc)[4][2][4],
    u32 a_hi_b, u32 a_lo_b, int rowbytes,
    const u16* __restrict__ Whs,
    int nc, u32 wbase, int lane)
{
    stage_ws_hi(wbase, Whs, 0, lane);
    CPCOMMIT();
    u32 ah[4][4], al[4][4], bh[4];
    for (int c = 0; c < nc; c++) {
        if (c + 1 < nc) {
            stage_ws_hi(wbase + (u32)(((c + 1) & 1) * 1536), Whs, c + 1, lane);
            CPCOMMIT();
            CPWAIT1();
        } else {
            CPWAIT0();
        }
        __syncwarp();
        const u32 cur = wbase + (u32)((c & 1) * 1536);
#pragma unroll
        for (int ks = 0; ks < 2; ks++) {
            const u32 aoff = (u32)(c * 64 + ks * 32);
#pragma unroll
            for (int mt = 0; mt < 4; mt++) {
                ldsm4(ah[mt], a_hi_b + (u32)(mt * 16 * rowbytes) + aoff);
                ldsm4(al[mt], a_lo_b + (u32)(mt * 16 * rowbytes) + aoff);
            }
            const u32 baddr = cur + (u32)((ks * 16 + (lane & 15)) * 48
                                          + (lane >> 4) * 16);
            ldsm4t(bh, baddr);
#pragma unroll
            for (int mt = 0; mt < 4; mt++)
#pragma unroll
                for (int nb = 0; nb < 2; nb++) {
                    const u32 b0 = bh[2 * nb], b1 = bh[2 * nb + 1];
                    mma_f16(acc[mt][nb], ah[mt][0], ah[mt][1], ah[mt][2], ah[mt][3], b0, b1);
                    mma_f16(acc[mt][nb], al[mt][0], al[mt][1], al[mt][2], al[mt][3], b0, b1);
                }
        }
    }
}

__device__ __forceinline__ void zero_acc_tc(float (&acc)[4][2][4]) {
#pragma unroll
    for (int mt = 0; mt < 4; mt++)
#pragma unroll
        for (int nb = 0; nb < 2; nb++)
#pragma unroll
            for (int q = 0; q < 4; q++) acc[mt][nb][q] = 0.f;
}

// epilogue: relu(acc+bias) -> split fp16 hi/lo planes (stride 264)
__device__ __forceinline__ void epi_relu(const float (&acc)[4][2][4],
                                         const float* __restrict__ bias,
                                         u16* a_hi, u16* a_lo, int tid) {
    const int lane = tid & 31, wid = tid >> 5;
    const int n_off = wid * 16;
    const int g = lane >> 2, tt = lane & 3;
#pragma unroll
    for (int mt = 0; mt < 4; mt++)
#pragma unroll
        for (int nb = 0; nb < 2; nb++) {
            const int c = n_off + nb * 8 + 2 * tt;
            const float b0 = bias[c], b1 = bias[c + 1];
            const int rlo = mt * 16 + g, rhi = rlo + 8;
            float v0 = fmaxf(acc[mt][nb][0] + b0, 0.f);
            float v1 = fmaxf(acc[mt][nb][1] + b1, 0.f);
            float v2 = fmaxf(acc[mt][nb][2] + b0, 0.f);
            float v3 = fmaxf(acc[mt][nb][3] + b1, 0.f);
            __half2 h01 = __floats2half2_rn(v0, v1);
            __half2 h23 = __floats2half2_rn(v2, v3);
            float2 hf01 = __half22float2(h01);
            float2 hf23 = __half22float2(h23);
            __half2 l01 = __floats2half2_rn(v0 - hf01.x, v1 - hf01.y);
            __half2 l23 = __floats2half2_rn(v2 - hf23.x, v3 - hf23.y);
            *(u32*)(a_hi + rlo * 264 + c) = *(u32*)&h01;
            *(u32*)(a_hi + rhi * 264 + c) = *(u32*)&h23;
            *(u32*)(a_lo + rlo * 264 + c) = *(u32*)&l01;
            *(u32*)(a_lo + rhi * 264 + c) = *(u32*)&l23;
        }
}

// gate GEMM2 epilogue: h2 = acc + bias (fp32, stride 260, no relu)
__device__ __forceinline__ void epi_h2(const float (&acc)[4][2][4],
                                       const float* __restrict__ bias,
                                       float* h2, int tid) {
    const int lane = tid & 31, wid = tid >> 5;
    const int n_off = wid * 16;
    const int g = lane >> 2, tt = lane & 3;
#pragma unroll
    for (int mt = 0; mt < 4; mt++)
#pragma unroll
        for (int nb = 0; nb < 2; nb++) {
            const int c = n_off + nb * 8 + 2 * tt;
            const float b0 = bias[c], b1 = bias[c + 1];
            const int rlo = mt * 16 + g, rhi = rlo + 8;
            h2[rlo * 260 + c]     = acc[mt][nb][0] + b0;
            h2[rlo * 260 + c + 1] = acc[mt][nb][1] + b1;
            h2[rhi * 260 + c]     = acc[mt][nb][2] + b0;
            h2[rhi * 260 + c + 1] = acc[mt][nb][3] + b1;
        }
}

// ---------------- kernel 0: reset ---------------------------------------------
__global__ void reset_kernel() {
    if (threadIdx.x < NE) g_count[threadIdx.x] = 0;
}

// ---------------- kernel 0b: split expert weights to fp16 hi/lo ----------------
__global__ void convert_weights(
    const float* __restrict__ ew0, const float* __restrict__ ew1,
    const float* __restrict__ ew2, const float* __restrict__ ew3,
    const float* __restrict__ ew4, const float* __restrict__ ew5,
    const float* __restrict__ ew6) {
    int idx = blockIdx.x * 256 + threadIdx.x;          // < NE*WROWS*256
    int e   = idx / (WROWS * 256);
    int rem = idx - e * (WROWS * 256);
    int r = rem >> 8, n = rem & 255;
    float w = 0.f;
    if (r < 96)        { int k = r;            if (k < 95) w = ew0[((size_t)e * 95 + k) * 256 + n]; }
    else if (r < 352)  { int k = r - 96;       w = ew1[((size_t)e * 256 + k) * 256 + n]; }
    else if (r < 608)  { int k = r - 352;      w = ew2[((size_t)e * 256 + k) * 256 + n]; }
    else if (r < 864)  { int k = r - 608;      w = ew3[((size_t)e * 256 + k) * 256 + n]; }
    else if (r < 1120) { int k = r - 864;      w = ew4[((size_t)e * 256 + k) * 256 + n]; }
    else if (r < 1376) { int k = r - 1120;     w = ew5[((size_t)e * 351 + k) * 256 + n]; }
    else if (r < 1472) { int k = 256 + (r - 1376); if (k < 351) w = ew5[((size_t)e * 351 + k) * 256 + n]; }
    else               { int k = r - 1472;     w = ew6[((size_t)e * 256 + k) * 256 + n]; }
    split2h(w, g_wh[idx], g_wl[idx]);
}

// ---------------- kernel 0c: split gate weights --------------------------------
__global__ void convert_gate_weights(const float* __restrict__ gw1,
                                     const float* __restrict__ gw2) {
    int idx = blockIdx.x * 256 + threadIdx.x;          // < GWROWS*256
    int r = idx >> 8, n = idx & 255;
    float w = 0.f;
    if (r < 320) { if (r < 319) w = gw1[(size_t)r * 256 + n]; }
    else         w = gw2[(size_t)(r - 320) * 256 + n];
    split2h(w, g_gh[idx], g_gl[idx]);
}

// ---------------- kernel 1: gate network + routing (TC fp16-split) -------------
// smem bytes: region0 [0, 84992): gi planes (2 x 64x328 u16) -> h1 planes
//             (2 x 64x264 u16) -> h2 fp32 (64x260) + logits (at 66560)
//             per-warp wst at 84992: 16 x 6144 B; gw3t aliases wst after GEMMs
#define GATE_SMEM_B (84992 + 98304)

__global__ __launch_bounds__(NT, 1) void gate_kernel(
    const float* __restrict__ x,  const float* __restrict__ sl,
    const float* __restrict__ gb1, const float* __restrict__ gb2,
    const float* __restrict__ lng, const float* __restrict__ lnb,
    const float* __restrict__ gw3, const float* __restrict__ gb3) {
    extern __shared__ u16 smu[];
    u16* gi_hi = smu;                       // 64*328
    u16* gi_lo = smu + 20992;
    u16* a_hi  = smu;                       // 64*264 (after GEMM1)
    u16* a_lo  = smu + 16896;
    float* h2    = (float*)smu;             // 64*260 (after GEMM2)
    float* lgbuf = (float*)((char*)smu + 66560);   // 64*8
    float* gw3t  = (float*)((char*)smu + 84992);   // 8*256 (aliases wst)
    const u32 wstu = (u32)__cvta_generic_to_shared((char*)smu + 84992);

    const int tid = threadIdx.x;
    const int row0 = blockIdx.x * 64;
    const int lane = tid & 31, wid = tid >> 5;
    const u32 wbase = wstu + (u32)(wid * 6144);

    // gather g_in = concat(x, shape_latent) -> fp16 hi/lo planes (stride 328)
    // divide-free: 8 threads per row, columns strided by 8
    {
        int r = tid >> 3, sub = tid & 7;
        int gi = row0 + r;
        u16* gh = gi_hi + r * 328;
        u16* gl = gi_lo + r * 328;
        for (int c = sub; c < 328; c += 8) {
            float v = 0.f;
            if (c < 63)       v = x[(size_t)gi * 63 + c];
            else if (c < 319) v = sl[(size_t)gi * 256 + (c - 63)];
            split2h(v, gh[c], gl[c]);
        }
    }
    __syncthreads();

    const u32 gihi_b = (u32)__cvta_generic_to_shared(gi_hi)
                     + (u32)((lane & 15) * 656) + (u32)((lane >> 4) * 16);
    const u32 gilo_b = (u32)__cvta_generic_to_shared(gi_lo)
                     + (u32)((lane & 15) * 656) + (u32)((lane >> 4) * 16);
    const u32 ahi_b = (u32)__cvta_generic_to_shared(a_hi)
                    + (u32)((lane & 15) * 528) + (u32)((lane >> 4) * 16);
    const u32 alo_b = (u32)__cvta_generic_to_shared(a_lo)
                    + (u32)((lane & 15) * 528) + (u32)((lane >> 4) * 16);

    float acc[4][2][4];

    // GEMM1: g_in (K=320) @ gw1 -> relu -> h1 split planes  (10 chunks, no bar)
    zero_acc_tc(acc);
    gemm_ws(acc, gihi_b, gilo_b, 656, g_gh + wid * 16, g_gl + wid * 16,
            10, wbase, lane);
    __syncthreads();
    epi_relu(acc, gb1, a_hi, a_lo, tid);
    __syncthreads();

    // GEMM2: h1 (K=256) @ gw2 -> h2 fp32  (8 chunks, no bar)
    zero_acc_tc(acc);
    gemm_ws(acc, ahi_b, alo_b, 528, g_gh + 320 * 256 + wid * 16,
            g_gl + 320 * 256 + wid * 16, 8, wbase, lane);
    __syncthreads();
    epi_h2(acc, gb2, h2, tid);
    __syncthreads();

    // LayerNorm per row: 8 threads/row, two-pass (stride 260)
    {
        int r = tid >> 3, sub = tid & 7;
        float* h2r = h2 + r * 260;
        float s = 0.f;
#pragma unroll 8
        for (int k = 0; k < 32; k++) s += h2r[sub + 8 * k];
        s += __shfl_xor_sync(0xffffffffu, s, 1);
        s += __shfl_xor_sync(0xffffffffu, s, 2);
        s += __shfl_xor_sync(0xffffffffu, s, 4);
        float mu = s * (1.f / 256.f);
        float vv = 0.f;
#pragma unroll 8
        for (int k = 0; k < 32; k++) {
            float d = h2r[sub + 8 * k] - mu;
            vv += d * d;
        }
        vv += __shfl_xor_sync(0xffffffffu, vv, 1);
        vv += __shfl_xor_sync(0xffffffffu, vv, 2);
        vv += __shfl_xor_sync(0xffffffffu, vv, 4);
        float rstd = rsqrtf(vv * (1.f / 256.f) + 1e-5f);
#pragma unroll 8
        for (int k = 0; k < 32; k++) {
            int c = sub + 8 * k;
            float nv = (h2r[c] - mu) * rstd;
            h2r[c] = nv * lng[c] + lnb[c];
        }
    }
    // stage gw3 transposed [e][k] into (now idle) wst region
    for (int i = tid; i < 2048; i += NT) {
        int e = i >> 8, k = i & 255;
        gw3t[i] = gw3[k * 8 + e];
    }
    __syncthreads();

    // logits = h2 @ gw3 + gb3 (float4 smem dot; one task per thread)
    {
        int r = tid >> 3, e = tid & 7;
        float d = gb3[e];
        const float4* h4 = (const float4*)(h2 + r * 260);
        const float4* w4 = (const float4*)(gw3t + e * 256);
#pragma unroll 8
        for (int k = 0; k < 64; k++) {
            float4 a = h4[k], w = w4[k];
            d += a.x * w.x; d += a.y * w.y; d += a.z * w.z; d += a.w * w.w;
        }
        lgbuf[r * 8 + e] = d;
    }
    __syncthreads();

    // softmax / argmax / append to expert list
    if (tid < 64) {
        int gi = row0 + tid;
        const float* lg = lgbuf + tid * 8;
        float best = lg[0];
        int bi = 0;
#pragma unroll
        for (int e = 1; e < 8; e++) {
            float v = lg[e];
            if (v > best) { best = v; bi = e; }
        }
        float ssum = 0.f;
#pragma unroll
        for (int e = 0; e < 8; e++) ssum += expf(lg[e] - best);
        g_gv[gi] = 1.f / ssum;
        int pos = atomicAdd(&g_count[bi], 1);
        g_list[bi][pos] = gi;
    }
}

// ---------------- kernel 2: routed expert MLP (TC, warp-decoupled, 2-term) ----
// smem: a_hi[16896] a_lo[16896] h_hi[6656] h_lo[6656] (u16) | wst 16 x 3072 B
#define EXP_SMEM_B ((16896 * 2 + 6656 * 2) * 2 + 49152)
#define EXP_TILES  (BPTS / 64 + NE)

__global__ __launch_bounds__(NT, 1) void expert_kernel(
    const float* __restrict__ x,  const float* __restrict__ sl,
    const float* __restrict__ eb0, const float* __restrict__ eb1,
    const float* __restrict__ eb2, const float* __restrict__ eb3,
    const float* __restrict__ eb4, const float* __restrict__ eb5,
    const float* __restrict__ eb6,
    const float* __restrict__ ewo, const float* __restrict__ ebo,
    float* __restrict__ out) {
    int t = blockIdx.x;
    int e, base = 0, n = 0;
    for (e = 0; e < NE; e++) {
        n = g_count[e];
        int T = (n + 63) >> 6;
        if (t < base + T) break;
        base += T;
    }
    if (e == NE) return;
    const int start = (t - base) * 64;
    const int nrows = min(64, n - start);

    extern __shared__ u16 smu[];
    u16* a_hi = smu;                    // 64*264
    u16* a_lo = smu + 16896;
    u16* h_hi = smu + 2 * 16896;        // 64*104
    u16* h_lo = h_hi + 6656;
    const u32 wstu = (u32)__cvta_generic_to_shared(smu + 2 * 16896 + 2 * 6656);
    __shared__ int ridx[64];
    const int tid = threadIdx.x;
    const int lane = tid & 31, wid = tid >> 5;
    const u32 wbase = wstu + (u32)(wid * 3072);

    if (tid < 64) ridx[tid] = (tid < nrows) ? g_list[e][start + tid] : -1;
    __syncthreads();

    // gather h0 = concat(x, latent chunk e) -> fp16 hi/lo planes (divide-free)
    {
        int r = tid >> 3, sub = tid & 7;
        int gi = ridx[r];
        u16* hh = h_hi + r * 104;
        u16* hl = h_lo + r * 104;
        for (int c = sub; c < 104; c += 8) {
            float v = 0.f;
            if (gi >= 0) {
                if (c < 63)      v = x[(size_t)gi * 63 + c];
                else if (c < 95) v = sl[(size_t)gi * 256 + e * CHUNKD + (c - 63)];
            }
            split2h(v, hh[c], hl[c]);
        }
    }
    __syncthreads();

    const u32 a_hi_b = (u32)__cvta_generic_to_shared(a_hi)
                     + (u32)((lane & 15) * 528) + (u32)((lane >> 4) * 16);
    const u32 a_lo_b = (u32)__cvta_generic_to_shared(a_lo)
                     + (u32)((lane & 15) * 528) + (u32)((lane >> 4) * 16);
    const u32 h_hi_b = (u32)__cvta_generic_to_shared(h_hi)
                     + (u32)((lane & 15) * 208) + (u32)((lane >> 4) * 16);
    const u32 h_lo_b = (u32)__cvta_generic_to_shared(h_lo)
                     + (u32)((lane & 15) * 208) + (u32)((lane >> 4) * 16);

    const u16* WH = g_wh + (size_t)e * WROWS * 256 + wid * 16;
    float acc[4][2][4];

    // L0: h0 (K=96) -> 256  (3 chunks, no bar)
    zero_acc_tc(acc);
    gemm_ws2(acc, h_hi_b, h_lo_b, 208, WH, 3, wbase, lane);
    __syncthreads();
    epi_relu(acc, eb0 + e * 256, a_hi, a_lo, tid);
    __syncthreads();

    // L1..L4: 256 -> 256  (8 chunks each, no bar)
    const float* bl4[4] = { eb1, eb2, eb3, eb4 };
#pragma unroll 1
    for (int l = 0; l < 4; l++) {
        zero_acc_tc(acc);
        gemm_ws2(acc, a_hi_b, a_lo_b, 528,
                 WH + (size_t)(96 + l * 256) * 256, 8, wbase, lane);
        __syncthreads();
        epi_relu(acc, bl4[l] + e * 256, a_hi, a_lo, tid);
        __syncthreads();
    }

    // L5 (skip): act part (K=256) + h0 part (K=96); per-warp, no bar
    zero_acc_tc(acc);
    gemm_ws2(acc, a_hi_b, a_lo_b, 528, WH + (size_t)1120 * 256, 8, wbase, lane);
    gemm_ws2(acc, h_hi_b, h_lo_b, 208, WH + (size_t)1376 * 256, 3, wbase, lane);
    __syncthreads();
    epi_relu(acc, eb5 + e * 256, a_hi, a_lo, tid);
    __syncthreads();

    // L6
    zero_acc_tc(acc);
    gemm_ws2(acc, a_hi_b, a_lo_b, 528, WH + (size_t)1472 * 256, 8, wbase, lane);
    __syncthreads();
    epi_relu(acc, eb6 + e * 256, a_hi, a_lo, tid);
    __syncthreads();

    // output head: y = act @ ewo[e] + ebo[e]; combine with gate
    if (tid < 256) {
        int r = tid >> 2, o = tid & 3;
        if (r < nrows) {
            float d = ebo[e * 4 + o];
            const float* wo = ewo + (size_t)e * 1024 + o;
            const __half2* ah2 = (const __half2*)(a_hi + r * 264);
            const __half2* al2 = (const __half2*)(a_lo + r * 264);
#pragma unroll 8
            for (int k = 0; k < 128; k++) {
                float2 hv = __half22float2(ah2[k]);
                float2 lv = __half22float2(al2[k]);
                d += (hv.x + lv.x) * wo[(2 * k) * 4];
                d += (hv.y + lv.y) * wo[(2 * k + 1) * 4];
            }
            int gi = ridx[r];
            float comb = g_gv[gi] * expf(d);
            if (comb == 0.f) comb = EPSF;
            out[gi * 4 + o] = logf(comb);
        }
    }
}

// ---------------- launch -----------------------------------------------------
extern "C" void kernel_launch(void* const* d_in, const int* in_sizes, int n_in,
                              void* d_out, int out_size) {
    const float* x   = (const float*)d_in[0];
    const float* sl  = (const float*)d_in[1];
    const float* gw1 = (const float*)d_in[2];
    const float* gb1 = (const float*)d_in[3];
    const float* gw2 = (const float*)d_in[4];
    const float* gb2 = (const float*)d_in[5];
    const float* lng = (const float*)d_in[6];
    const float* lnb = (const float*)d_in[7];
    const float* gw3 = (const float*)d_in[8];
    const float* gb3 = (const float*)d_in[9];
    const float* ew0 = (const float*)d_in[10];
    const float* eb0 = (const float*)d_in[11];
    const float* ew1 = (const float*)d_in[12];
    const float* eb1 = (const float*)d_in[13];
    const float* ew2 = (const float*)d_in[14];
    const float* eb2 = (const float*)d_in[15];
    const float* ew3 = (const float*)d_in[16];
    const float* eb3 = (const float*)d_in[17];
    const float* ew4 = (const float*)d_in[18];
    const float* eb4 = (const float*)d_in[19];
    const float* ew5 = (const float*)d_in[20];
    const float* eb5 = (const float*)d_in[21];
    const float* ew6 = (const float*)d_in[22];
    const float* eb6 = (const float*)d_in[23];
    const float* ewo = (const float*)d_in[24];
    const float* ebo = (const float*)d_in[25];
    float* out = (float*)d_out;

    static cudaStream_t s2 = nullptr;
    static cudaEvent_t evFork = nullptr, evJoin = nullptr;
    if (s2 == nullptr) {
        cudaStreamCreateWithFlags(&s2, cudaStreamNonBlocking);
        cudaEventCreateWithFlags(&evFork, cudaEventDisableTiming);
        cudaEventCreateWithFlags(&evJoin, cudaEventDisableTiming);
        cudaFuncSetAttribute(gate_kernel,
                             cudaFuncAttributeMaxDynamicSharedMemorySize, GATE_SMEM_B);
        cudaFuncSetAttribute(expert_kernel,
                             cudaFuncAttributeMaxDynamicSharedMemorySize, EXP_SMEM_B);
    }

    // fork: expert-weight conversion runs concurrently with the gate path
    cudaEventRecord(evFork, 0);
    cudaStreamWaitEvent(s2, evFork, 0);
    convert_weights<<<NE * WROWS, 256, 0, s2>>>(ew0, ew1, ew2, ew3, ew4, ew5, ew6);
    cudaEventRecord(evJoin, s2);

    // main path: reset + gate weights + gate
    reset_kernel<<<1, 32>>>();
    convert_gate_weights<<<GWROWS, 256>>>(gw1, gw2);
    gate_kernel<<<BPTS / 64, NT, GATE_SMEM_B>>>(x, sl, gb1, gb2,
                                                lng, lnb, gw3, gb3);

    // join: expert needs g_wh/g_wl
    cudaStreamWaitEvent(0, evJoin, 0);
    expert_kernel<<<EXP_TILES, NT, EXP_SMEM_B>>>(
        x, sl, eb0, eb1, eb2, eb3, eb4, eb5, eb6, ewo, ebo, out);
}